// round 14
// baseline (speedup 1.0000x reference)
#include <cuda_runtime.h>
#include <cuda_bf16.h>
#include <math.h>
#include <stdint.h>

#define B_   4
#define S_   256
#define V_   64
#define LP1_ 11
#define H_   128
#define NH_  8
#define DH_  16
#define NL_  3
#define M_   (B_*S_)   // 1024

// ---------------- scratch (device globals; no allocation) ----------------
__device__ float g_adjT[V_*LP1_*V_];
__device__ float g_z [M_*V_*H_];
__device__ float g_z2[M_*V_*H_];
__device__ float g_qkv[3*M_*V_*H_];
__device__ __align__(16) __nv_bfloat16 g_whi[7*V_*H_*H_];   // W^T[slot*64+v][n][k]
__device__ __align__(16) __nv_bfloat16 g_wlo[7*V_*H_*H_];

// ---------------- pack helpers --------------------------------------------
__device__ __forceinline__ uint32_t pkrn(float x, float y) {
    __nv_bfloat162 h = __floats2bfloat162_rn(x, y);
    return *(uint32_t*)&h;
}
__device__ __forceinline__ uint32_t pklo(float x, float y, uint32_t hi) {
    __nv_bfloat162 h = *(__nv_bfloat162*)&hi;
    return pkrn(x - __bfloat162float(h.x), y - __bfloat162float(h.y));
}
// truncation split: hi = top16(f) exactly, lo = trunc16(f - hi)
__device__ __forceinline__ void pack_trunc2(float a, float b, uint32_t& h, uint32_t& l) {
    uint32_t ba = __float_as_uint(a), bb = __float_as_uint(b);
    h = __byte_perm(ba, bb, 0x7632);
    float ra = a - __uint_as_float(ba & 0xFFFF0000u);
    float rb = b - __uint_as_float(bb & 0xFFFF0000u);
    l = __byte_perm(__float_as_uint(ra), __float_as_uint(rb), 0x7632);
}

__device__ __forceinline__ uint32_t smem_u32(const void* p) {
    uint32_t a;
    asm("{ .reg .u64 t; cvta.to.shared.u64 t, %1; cvt.u32.u64 %0, t; }" : "=r"(a) : "l"(p));
    return a;
}
__device__ __forceinline__ void cpa16(uint32_t dst, const void* src) {
    asm volatile("cp.async.ca.shared.global [%0], [%1], 16;" :: "r"(dst), "l"(src));
}
#define CP_COMMIT() asm volatile("cp.async.commit_group;" ::: "memory")
#define CP_WAIT(n)  asm volatile("cp.async.wait_group %0;" :: "n"(n) : "memory")

// mma.sync m16n8k16 row.col bf16 -> f32 accumulate in place
__device__ __forceinline__ void mma16816(float* c, const uint32_t* a, uint32_t b0, uint32_t b1) {
    asm volatile(
        "mma.sync.aligned.m16n8k16.row.col.f32.bf16.bf16.f32 "
        "{%0,%1,%2,%3}, {%4,%5,%6,%7}, {%8,%9}, {%0,%1,%2,%3};\n"
        : "+f"(c[0]), "+f"(c[1]), "+f"(c[2]), "+f"(c[3])
        : "r"(a[0]), "r"(a[1]), "r"(a[2]), "r"(a[3]), "r"(b0), "r"(b1));
}

// ---------------- stage 0: sigmoid + transpose of adjacency --------------
__global__ void prep_adj_kernel(const float* __restrict__ logits, float* __restrict__ adjT) {
    int idx = blockIdx.x * 256 + threadIdx.x;
    if (idx >= V_*V_*LP1_) return;
    int s = idx % V_;
    int r = idx / V_;
    int l = r % LP1_;
    int i = r / LP1_;
    float x = logits[(s*V_ + i)*LP1_ + l];
    adjT[idx] = 1.f / (1.f + __expf(-x));
}

// ------- weight transpose+split: wt[slot*64+v][n][k] = W[..][k][n] --------
__global__ void prep_w_kernel(const float* __restrict__ mW,
                              const float* __restrict__ Wq, const float* __restrict__ Wk,
                              const float* __restrict__ Wv, const float* __restrict__ Wo,
                              __nv_bfloat16* __restrict__ whi, __nv_bfloat16* __restrict__ wlo) {
    int sv = blockIdx.z;                 // 0..447
    int s = sv >> 6, v = sv & 63;
    const float* src;
    if (s < 3)       src = mW + ((size_t)(v*NL_ + s))*H_*H_;
    else if (s == 3) src = Wq + (size_t)v*H_*H_;
    else if (s == 4) src = Wk + (size_t)v*H_*H_;
    else if (s == 5) src = Wv + (size_t)v*H_*H_;
    else             src = Wo + (size_t)v*H_*H_;
    __shared__ float t[32][33];
    int nbase = blockIdx.x*32, kbase = blockIdx.y*32;
    int tx = threadIdx.x, ty = threadIdx.y;
    #pragma unroll
    for (int j = 0; j < 4; j++)
        t[ty + j*8][tx] = src[(size_t)(kbase + ty + j*8)*H_ + nbase + tx];
    __syncthreads();
    size_t obase = (size_t)sv*H_*H_;
    #pragma unroll
    for (int j = 0; j < 4; j++) {
        int n = nbase + ty + j*8;
        int k = kbase + tx;
        float f = t[tx][ty + j*8];
        __nv_bfloat16 hb = __float2bfloat16(f);
        float rl = f - __bfloat162float(hb);
        __nv_bfloat16 lb = __float2bfloat16(rl);
        whi[obase + (size_t)n*H_ + k] = hb;
        wlo[obase + (size_t)n*H_ + k] = lb;
    }
}

// ---------------- stage 1: z[b,t,i,h] -------------------------------------
__global__ __launch_bounds__(256)
void stage1_kernel(const float* __restrict__ x, const float* __restrict__ adjT,
                   const float* __restrict__ var_emb, const float* __restrict__ temp_emb,
                   float* __restrict__ z) {
    int bt = blockIdx.x;
    int b = bt >> 8;
    int t = bt & 255;
    __shared__ float xw[LP1_][V_];
    __shared__ float Am[V_][V_ + 1];
    __shared__ float Bls[V_][LP1_ + 1];
    int tid = threadIdx.x;

    for (int p = tid; p < LP1_*V_; p += 256) {
        int l = p / V_, s = p % V_;
        int tt = t - l;
        xw[l][s] = (tt >= 0) ? x[((size_t)(b*S_ + tt))*V_ + s] : 0.f;
    }
    __syncthreads();

    for (int p = tid; p < V_*V_; p += 256) {
        int i = p >> 6, s = p & 63;
        const float* ap = adjT + (size_t)i*LP1_*V_ + s;
        float a = 0.f;
        #pragma unroll
        for (int l = 0; l < LP1_; l++) a += xw[l][s] * ap[l*V_];
        Am[i][s] = a;
    }
    for (int p = tid; p < V_*LP1_; p += 256) {
        int i = p / LP1_, l = p % LP1_;
        const float* ap = adjT + ((size_t)i*LP1_ + l)*V_;
        float a = 0.f;
        #pragma unroll 8
        for (int s = 0; s < V_; s++) a += xw[l][s] * ap[s];
        Bls[i][l] = a;
    }
    __syncthreads();

    int tx = tid & 15, ty = tid >> 4;
    float acc[4][8];
    #pragma unroll
    for (int r = 0; r < 4; r++)
        #pragma unroll
        for (int c = 0; c < 8; c++) acc[r][c] = 0.f;

    for (int s = 0; s < V_; s++) {
        float a0 = Am[ty*4+0][s], a1 = Am[ty*4+1][s], a2 = Am[ty*4+2][s], a3 = Am[ty*4+3][s];
        const float4* vp = (const float4*)(var_emb + (size_t)s*H_ + tx*8);
        float4 v0 = vp[0], v1 = vp[1];
        float bv[8] = {v0.x,v0.y,v0.z,v0.w,v1.x,v1.y,v1.z,v1.w};
        #pragma unroll
        for (int c = 0; c < 8; c++) {
            acc[0][c] += a0*bv[c]; acc[1][c] += a1*bv[c];
            acc[2][c] += a2*bv[c]; acc[3][c] += a3*bv[c];
        }
    }
    #pragma unroll
    for (int l = 0; l < LP1_; l++) {
        float a0 = Bls[ty*4+0][l], a1 = Bls[ty*4+1][l], a2 = Bls[ty*4+2][l], a3 = Bls[ty*4+3][l];
        const float4* vp = (const float4*)(temp_emb + (size_t)l*H_ + tx*8);
        float4 v0 = vp[0], v1 = vp[1];
        float bv[8] = {v0.x,v0.y,v0.z,v0.w,v1.x,v1.y,v1.z,v1.w};
        #pragma unroll
        for (int c = 0; c < 8; c++) {
            acc[0][c] += a0*bv[c]; acc[1][c] += a1*bv[c];
            acc[2][c] += a2*bv[c]; acc[3][c] += a3*bv[c];
        }
    }
    #pragma unroll
    for (int r = 0; r < 4; r++) {
        int i = ty*4 + r;
        float* zp = z + ((size_t)bt*V_ + i)*H_ + tx*8;
        *(float4*)(zp)   = make_float4(acc[r][0], acc[r][1], acc[r][2], acc[r][3]);
        *(float4*)(zp+4) = make_float4(acc[r][4], acc[r][5], acc[r][6], acc[r][7]);
    }
}

// ========= register-resident GEMM: warp = 16 rows x 128 cols ===============
// smem: params 4608 + 2 W ring buffers of (hi 10240 | lo 10240)
#define FP_PAR 0
#define WS0    4608
#define WSHALF 10240
#define WS1    (WS0 + 2*WSHALF)   // 25088
#define FGSM   (WS1 + 2*WSHALF)   // 45568
#define PW     20                 // u32 words per n-row in staged W (conflict-free)

// stage one 32-k chunk of W^T (hi+lo): tid = n row (128 threads)
__device__ __forceinline__ void stageW(uint32_t sb, const __nv_bfloat16* __restrict__ hi,
                                       const __nv_bfloat16* __restrict__ lo,
                                       int chunk, int tid) {
    const __nv_bfloat16* srcH = hi + (size_t)tid*H_ + chunk*32;
    const __nv_bfloat16* srcL = lo + (size_t)tid*H_ + chunk*32;
    uint32_t dst = sb + tid*(PW*4);
    #pragma unroll
    for (int seg = 0; seg < 4; seg++) {
        cpa16(dst + seg*16, srcH + seg*8);
        cpa16(dst + WSHALF + seg*16, srcL + seg*8);
    }
}

// one GEMM layer: y (A, 16 rows x 128 cols in regs) -> C (+=), W^T from gmem
__device__ __forceinline__ void gemm_layer(char* smem, uint32_t sbase,
        const __nv_bfloat16* __restrict__ wtH, const __nv_bfloat16* __restrict__ wtL,
        const float (&y)[64], float (&C)[64], int tid, int lane) {
    #pragma unroll
    for (int i = 0; i < 64; i++) C[i] = 0.f;
    const int bufs[2] = {WS0, WS1};
    stageW(sbase + WS0, wtH, wtL, 0, tid);
    CP_COMMIT();
    int qd = lane >> 2, m = lane & 3;
    #pragma unroll
    for (int c = 0; c < 4; c++) {
        if (c < 3) {
            stageW(sbase + bufs[(c+1)&1], wtH, wtL, c+1, tid);
            CP_COMMIT();
            CP_WAIT(1);
        } else {
            CP_WAIT(0);
        }
        __syncthreads();
        const uint32_t* wsH = (const uint32_t*)(smem + bufs[c&1]);
        const uint32_t* wsL = (const uint32_t*)(smem + bufs[c&1] + WSHALF);
        #pragma unroll
        for (int s2 = 0; s2 < 2; s2++) {
            int kg = c*2 + s2;
            uint32_t ah[4], al[4];
            pack_trunc2(y[(2*kg)*4+0],   y[(2*kg)*4+1],   ah[0], al[0]);
            pack_trunc2(y[(2*kg)*4+2],   y[(2*kg)*4+3],   ah[1], al[1]);
            pack_trunc2(y[(2*kg+1)*4+0], y[(2*kg+1)*4+1], ah[2], al[2]);
            pack_trunc2(y[(2*kg+1)*4+2], y[(2*kg+1)*4+3], ah[3], al[3]);
            #pragma unroll
            for (int t = 0; t < 16; t++) {
                int wb = (t*8 + qd)*PW + s2*8 + m;
                uint32_t b0h = wsH[wb], b1h = wsH[wb+4];
                uint32_t b0l = wsL[wb], b1l = wsL[wb+4];
                mma16816(&C[t*4], ah, b0h, b1h);
                mma16816(&C[t*4], ah, b0l, b1l);
                mma16816(&C[t*4], al, b0h, b1h);
            }
        }
        __syncthreads();
    }
}

// load y (16 rows x 128) from gmem rows [row0, row0+8]
__device__ __forceinline__ void load_y(float (&y)[64], const float* __restrict__ a0,
                                       const float* __restrict__ a1, int m) {
    #pragma unroll
    for (int t = 0; t < 16; t++) {
        float2 r0 = *(const float2*)(a0 + m*2 + 8*t);
        float2 r1 = *(const float2*)(a1 + m*2 + 8*t);
        y[t*4+0] = r0.x; y[t*4+1] = r0.y; y[t*4+2] = r1.x; y[t*4+3] = r1.y;
    }
}

// bias + LN + GELU epilogue in registers (params from smem)
__device__ __forceinline__ void mech_epi(float (&C)[64], const float* sBias,
                                         const float* sG, const float* sBeta, int m) {
    float s0=0.f, q0=0.f, s1=0.f, q1=0.f;
    #pragma unroll
    for (int t = 0; t < 16; t++) {
        float2 bb = *(const float2*)(sBias + m*2 + 8*t);
        float y00 = C[t*4+0]+bb.x, y01 = C[t*4+1]+bb.y;
        float y10 = C[t*4+2]+bb.x, y11 = C[t*4+3]+bb.y;
        C[t*4+0]=y00; C[t*4+1]=y01; C[t*4+2]=y10; C[t*4+3]=y11;
        s0 += y00+y01; q0 += y00*y00+y01*y01;
        s1 += y10+y11; q1 += y10*y10+y11*y11;
    }
    s0 += __shfl_xor_sync(0xFFFFFFFFu, s0, 1); q0 += __shfl_xor_sync(0xFFFFFFFFu, q0, 1);
    s0 += __shfl_xor_sync(0xFFFFFFFFu, s0, 2); q0 += __shfl_xor_sync(0xFFFFFFFFu, q0, 2);
    s1 += __shfl_xor_sync(0xFFFFFFFFu, s1, 1); q1 += __shfl_xor_sync(0xFFFFFFFFu, q1, 1);
    s1 += __shfl_xor_sync(0xFFFFFFFFu, s1, 2); q1 += __shfl_xor_sync(0xFFFFFFFFu, q1, 2);
    float mean0 = s0*(1.f/128.f), var0 = q0*(1.f/128.f) - mean0*mean0;
    float mean1 = s1*(1.f/128.f), var1 = q1*(1.f/128.f) - mean1*mean1;
    float rs0 = rsqrtf(var0 + 1e-5f), rs1 = rsqrtf(var1 + 1e-5f);
    #pragma unroll
    for (int t = 0; t < 16; t++) {
        float2 gg = *(const float2*)(sG + m*2 + 8*t);
        float2 ll = *(const float2*)(sBeta + m*2 + 8*t);
        float t0 = (C[t*4+0]-mean0)*rs0*gg.x + ll.x;
        float t1 = (C[t*4+1]-mean0)*rs0*gg.y + ll.y;
        float t2 = (C[t*4+2]-mean1)*rs1*gg.x + ll.x;
        float t3 = (C[t*4+3]-mean1)*rs1*gg.y + ll.y;
        C[t*4+0] = 0.5f*t0*(1.f + erff(t0*0.7071067811865476f));
        C[t*4+1] = 0.5f*t1*(1.f + erff(t1*0.7071067811865476f));
        C[t*4+2] = 0.5f*t2*(1.f + erff(t2*0.7071067811865476f));
        C[t*4+3] = 0.5f*t3*(1.f + erff(t3*0.7071067811865476f));
    }
}

__device__ __forceinline__ void store_y(const float (&y)[64], float* __restrict__ o0,
                                        float* __restrict__ o1, int m) {
    #pragma unroll
    for (int t = 0; t < 16; t++) {
        *(float2*)(o0 + m*2 + 8*t) = make_float2(y[t*4+0], y[t*4+1]);
        *(float2*)(o1 + m*2 + 8*t) = make_float2(y[t*4+2], y[t*4+3]);
    }
}

// ---------------- fused 3-layer mech chain ---------------------------------
__global__ __launch_bounds__(128)
void fused_mech(const float* __restrict__ z, const float* __restrict__ mech_b,
                const float* __restrict__ lng, const float* __restrict__ lnb,
                const __nv_bfloat16* __restrict__ whi, const __nv_bfloat16* __restrict__ wlo,
                float* __restrict__ outz) {
    extern __shared__ char smem[];
    uint32_t sbase = smem_u32(smem);
    int tid = threadIdx.x, w = tid >> 5, lane = tid & 31;
    int v = blockIdx.y, m0 = blockIdx.x*64;
    int m = lane & 3;
    int row0 = m0 + w*16 + (lane >> 2);

    float* sBias = (float*)(smem + FP_PAR);
    float* sG    = sBias + 384;
    float* sBeta = sG + 384;
    #pragma unroll
    for (int li = 0; li < 3; li++) {
        sBias[li*128 + tid] = mech_b[(size_t)v*NL_*H_ + li*H_ + tid];
        sG[li*128 + tid]    = lng  [(size_t)v*NL_*H_ + li*H_ + tid];
        sBeta[li*128 + tid] = lnb  [(size_t)v*NL_*H_ + li*H_ + tid];
    }

    float y0[64], y1[64];
    load_y(y0, z + ((size_t)row0*V_ + v)*H_, z + ((size_t)(row0+8)*V_ + v)*H_, m);

    size_t wofs = (size_t)v*H_*H_;
    size_t slot = (size_t)V_*H_*H_;
    gemm_layer(smem, sbase, whi + wofs, wlo + wofs, y0, y1, tid, lane);
    mech_epi(y1, sBias, sG, sBeta, m);
    gemm_layer(smem, sbase, whi + slot + wofs, wlo + slot + wofs, y1, y0, tid, lane);
    mech_epi(y0, sBias + 128, sG + 128, sBeta + 128, m);
    gemm_layer(smem, sbase, whi + 2*slot + wofs, wlo + 2*slot + wofs, y0, y1, tid, lane);
    mech_epi(y1, sBias + 256, sG + 256, sBeta + 256, m);

    store_y(y1, outz + ((size_t)row0*V_ + v)*H_, outz + ((size_t)(row0+8)*V_ + v)*H_, m);
}

// ---------------- fused QKV -------------------------------------------------
__global__ __launch_bounds__(128)
void fused_qkv(const float* __restrict__ z2,
               const __nv_bfloat16* __restrict__ whi, const __nv_bfloat16* __restrict__ wlo,
               float* __restrict__ qkv) {
    extern __shared__ char smem[];
    uint32_t sbase = smem_u32(smem);
    int tid = threadIdx.x, w = tid >> 5, lane = tid & 31;
    int v = blockIdx.y, m0 = blockIdx.x*64;
    int m = lane & 3;
    int row0 = m0 + w*16 + (lane >> 2);

    float y[64], C[64];
    load_y(y, z2 + ((size_t)row0*V_ + v)*H_, z2 + ((size_t)(row0+8)*V_ + v)*H_, m);

    size_t slot = (size_t)V_*H_*H_;
    #pragma unroll
    for (int zi = 0; zi < 3; zi++) {
        size_t wofs = (size_t)(3+zi)*slot + (size_t)v*H_*H_;
        gemm_layer(smem, sbase, whi + wofs, wlo + wofs, y, C, tid, lane);
        float* o = qkv + (size_t)zi*M_*V_*H_;
        store_y(C, o + ((size_t)row0*V_ + v)*H_, o + ((size_t)(row0+8)*V_ + v)*H_, m);
    }
}

// ---------------- O-proj + output head --------------------------------------
__global__ __launch_bounds__(128)
void oproj_gemm(const float* __restrict__ att,
                const __nv_bfloat16* __restrict__ whi, const __nv_bfloat16* __restrict__ wlo,
                const float* __restrict__ bo, const float* __restrict__ oW,
                const float* __restrict__ oB, float* __restrict__ out) {
    extern __shared__ char smem[];
    uint32_t sbase = smem_u32(smem);
    int tid = threadIdx.x, w = tid >> 5, lane = tid & 31;
    int v = blockIdx.y, m0 = blockIdx.x*64;
    int m = lane & 3;
    int row0 = m0 + w*16 + (lane >> 2);

    float* sBias = (float*)(smem + FP_PAR);
    float* sG    = sBias + 384;
    sBias[tid] = bo[(size_t)v*H_ + tid];
    sG[tid]    = oW[(size_t)v*H_ + tid];

    float y[64], C[64];
    load_y(y, att + ((size_t)row0*V_ + v)*H_, att + ((size_t)(row0+8)*V_ + v)*H_, m);

    size_t wofs = (size_t)6*V_*H_*H_ + (size_t)v*H_*H_;
    gemm_layer(smem, sbase, whi + wofs, wlo + wofs, y, C, tid, lane);

    float p0 = 0.f, p1 = 0.f;
    #pragma unroll
    for (int t = 0; t < 16; t++) {
        float2 bb = *(const float2*)(sBias + m*2 + 8*t);
        float2 gg = *(const float2*)(sG + m*2 + 8*t);
        p0 += (C[t*4+0]+bb.x)*gg.x + (C[t*4+1]+bb.y)*gg.y;
        p1 += (C[t*4+2]+bb.x)*gg.x + (C[t*4+3]+bb.y)*gg.y;
    }
    p0 += __shfl_xor_sync(0xFFFFFFFFu, p0, 1);
    p0 += __shfl_xor_sync(0xFFFFFFFFu, p0, 2);
    p1 += __shfl_xor_sync(0xFFFFFFFFu, p1, 1);
    p1 += __shfl_xor_sync(0xFFFFFFFFu, p1, 2);
    if (m == 0) {
        float ob = oB[v];
        out[(size_t)row0*V_ + v]     = p0 + ob;
        out[(size_t)(row0+8)*V_ + v] = p1 + ob;
    }
}

// ================= flash-style mma attention ===============================
#define KSTR 12
#define VSTR 132

__global__ __launch_bounds__(256)
void attn_mma(const float* __restrict__ qkv,
              const float* __restrict__ bq, const float* __restrict__ bk,
              const float* __restrict__ bv, float* __restrict__ out) {
    __shared__ uint32_t khi[256*KSTR], klo[256*KSTR];
    __shared__ uint32_t vthi[16*VSTR], vtlo[16*VSTR];

    int bid = blockIdx.x;
    int n = bid & 7, v = (bid >> 3) & 63, b = bid >> 9;
    int tid = threadIdx.x, w = tid >> 5, lane = tid & 31;

    const float* q  = qkv;
    const float* kk = qkv + (size_t)M_*V_*H_;
    const float* vv = qkv + 2*(size_t)M_*V_*H_;
    size_t rstr = (size_t)V_*H_;
    size_t base = ((size_t)(b*S_)*V_ + v)*H_ + n*DH_;
    size_t bofs = (size_t)v*H_ + n*DH_;

    {
        int key = tid;
        const float4* kp = (const float4*)(kk + base + (size_t)key*rstr);
        const float4* vp = (const float4*)(vv + base + (size_t)key*rstr);
        float kr[16], vr[16];
        #pragma unroll
        for (int i = 0; i < 4; i++) {
            float4 a = kp[i], c = vp[i];
            float4 bb = *(const float4*)(bk + bofs + i*4);
            float4 cb = *(const float4*)(bv + bofs + i*4);
            kr[i*4+0]=a.x+bb.x; kr[i*4+1]=a.y+bb.y; kr[i*4+2]=a.z+bb.z; kr[i*4+3]=a.w+bb.w;
            vr[i*4+0]=c.x+cb.x; vr[i*4+1]=c.y+cb.y; vr[i*4+2]=c.z+cb.z; vr[i*4+3]=c.w+cb.w;
        }
        #pragma unroll
        for (int d = 0; d < 8; d++) {
            uint32_t h = pkrn(kr[2*d], kr[2*d+1]);
            khi[key*KSTR + d] = h;
            klo[key*KSTR + d] = pklo(kr[2*d], kr[2*d+1], h);
        }
        unsigned short* vthi16 = (unsigned short*)vthi;
        unsigned short* vtlo16 = (unsigned short*)vtlo;
        #pragma unroll
        for (int c = 0; c < 16; c++) {
            __nv_bfloat16 hb = __float2bfloat16(vr[c]);
            float lo = vr[c] - __bfloat162float(hb);
            __nv_bfloat16 lb = __float2bfloat16(lo);
            vthi16[c*(2*VSTR) + key] = __bfloat16_as_ushort(hb);
            vtlo16[c*(2*VSTR) + key] = __bfloat16_as_ushort(lb);
        }
    }

    int rq = w*32 + (lane >> 2);
    int c2 = (lane & 3) * 2;
    float2 bq0 = make_float2(bq[bofs + c2],     bq[bofs + c2 + 1]);
    float2 bq1 = make_float2(bq[bofs + c2 + 8], bq[bofs + c2 + 9]);
    uint32_t qhi[2][4], qlo[2][4];
    #pragma unroll
    for (int mi = 0; mi < 2; mi++) {
        int rA = rq + mi*16, rB = rA + 8;
        float2 x00 = *(const float2*)(q + base + (size_t)rA*rstr + c2);
        float2 x01 = *(const float2*)(q + base + (size_t)rA*rstr + c2 + 8);
        float2 x10 = *(const float2*)(q + base + (size_t)rB*rstr + c2);
        float2 x11 = *(const float2*)(q + base + (size_t)rB*rstr + c2 + 8);
        x00.x = (x00.x + bq0.x)*0.25f; x00.y = (x00.y + bq0.y)*0.25f;
        x01.x = (x01.x + bq1.x)*0.25f; x01.y = (x01.y + bq1.y)*0.25f;
        x10.x = (x10.x + bq0.x)*0.25f; x10.y = (x10.y + bq0.y)*0.25f;
        x11.x = (x11.x + bq1.x)*0.25f; x11.y = (x11.y + bq1.y)*0.25f;
        qhi[mi][0] = pkrn(x00.x, x00.y); qlo[mi][0] = pklo(x00.x, x00.y, qhi[mi][0]);
        qhi[mi][1] = pkrn(x10.x, x10.y); qlo[mi][1] = pklo(x10.x, x10.y, qhi[mi][1]);
        qhi[mi][2] = pkrn(x01.x, x01.y); qlo[mi][2] = pklo(x01.x, x01.y, qhi[mi][2]);
        qhi[mi][3] = pkrn(x11.x, x11.y); qlo[mi][3] = pklo(x11.x, x11.y, qhi[mi][3]);
    }
    __syncthreads();

    float oacc[2][2][4];
    #pragma unroll
    for (int mi = 0; mi < 2; mi++)
        #pragma unroll
        for (int d = 0; d < 2; d++)
            #pragma unroll
            for (int e = 0; e < 4; e++) oacc[mi][d][e] = 0.f;
    float mrun[2][2] = {{-1e30f,-1e30f},{-1e30f,-1e30f}};
    float lrun[2][2] = {{0.f,0.f},{0.f,0.f}};

    #pragma unroll
    for (int kt = 0; kt < 4; kt++) {
        int kb = kt * 64;
        uint32_t sbh[8][2], sbl[8][2];
        #pragma unroll
        for (int j = 0; j < 8; j++) {
            int key = kb + j*8 + (lane >> 2);
            int ci  = lane & 3;
            sbh[j][0] = khi[key*KSTR + ci];     sbh[j][1] = khi[key*KSTR + ci + 4];
            sbl[j][0] = klo[key*KSTR + ci];     sbl[j][1] = klo[key*KSTR + ci + 4];
        }
        #pragma unroll
        for (int mi = 0; mi < 2; mi++) {
            float C[8][4];
            #pragma unroll
            for (int j = 0; j < 8; j++) { C[j][0]=0.f; C[j][1]=0.f; C[j][2]=0.f; C[j][3]=0.f; }
            #pragma unroll
            for (int j = 0; j < 8; j++) {
                mma16816(C[j], qhi[mi], sbh[j][0], sbh[j][1]);
                mma16816(C[j], qhi[mi], sbl[j][0], sbl[j][1]);
                mma16816(C[j], qlo[mi], sbh[j][0], sbh[j][1]);
            }
            float mA = -1e30f, mB = -1e30f;
            #pragma unroll
            for (int j = 0; j < 8; j++) {
                mA = fmaxf(mA, fmaxf(C[j][0], C[j][1]));
                mB = fmaxf(mB, fmaxf(C[j][2], C[j][3]));
            }
            mA = fmaxf(mA, __shfl_xor_sync(0xFFFFFFFFu, mA, 1));
            mA = fmaxf(mA, __shfl_xor_sync(0xFFFFFFFFu, mA, 2));
            mB = fmaxf(mB, __shfl_xor_sync(0xFFFFFFFFu, mB, 1));
            mB = fmaxf(mB, __shfl_xor_sync(0xFFFFFFFFu, mB, 2));
            float nA = fmaxf(mrun[mi][0], mA), nB = fmaxf(mrun[mi][1], mB);
            float cA = __expf(mrun[mi][0] - nA), cB = __expf(mrun[mi][1] - nB);
            mrun[mi][0] = nA; mrun[mi][1] = nB;
            float sA = 0.f, sB = 0.f;
            #pragma unroll
            for (int j = 0; j < 8; j++) {
                C[j][0] = __expf(C[j][0] - nA); C[j][1] = __expf(C[j][1] - nA);
                C[j][2] = __expf(C[j][2] - nB); C[j][3] = __expf(C[j][3] - nB);
                sA += C[j][0] + C[j][1];
                sB += C[j][2] + C[j][3];
            }
            sA += __shfl_xor_sync(0xFFFFFFFFu, sA, 1);
            sA += __shfl_xor_sync(0xFFFFFFFFu, sA, 2);
            sB += __shfl_xor_sync(0xFFFFFFFFu, sB, 1);
            sB += __shfl_xor_sync(0xFFFFFFFFu, sB, 2);
            lrun[mi][0] = lrun[mi][0]*cA + sA;
            lrun[mi][1] = lrun[mi][1]*cB + sB;
            #pragma unroll
            for (int d = 0; d < 2; d++) {
                oacc[mi][d][0] *= cA; oacc[mi][d][1] *= cA;
                oacc[mi][d][2] *= cB; oacc[mi][d][3] *= cB;
            }
            #pragma unroll
            for (int u = 0; u < 4; u++) {
                uint32_t pa[4], pl[4];
                pa[0] = pkrn(C[2*u][0],   C[2*u][1]);   pl[0] = pklo(C[2*u][0],   C[2*u][1],   pa[0]);
                pa[1] = pkrn(C[2*u][2],   C[2*u][3]);   pl[1] = pklo(C[2*u][2],   C[2*u][3],   pa[1]);
                pa[2] = pkrn(C[2*u+1][0], C[2*u+1][1]); pl[2] = pklo(C[2*u+1][0], C[2*u+1][1], pa[2]);
                pa[3] = pkrn(C[2*u+1][2], C[2*u+1][3]); pl[3] = pklo(C[2*u+1][2], C[2*u+1][3], pa[3]);
                int kb2h = (kb + u*16) >> 1;
                #pragma unroll
                for (int d = 0; d < 2; d++) {
                    int nrow = d*8 + (lane >> 2);
                    uint32_t b0h = vthi[nrow*VSTR + kb2h + (lane & 3)];
                    uint32_t b1h = vthi[nrow*VSTR + kb2h + 4 + (lane & 3)];
                    uint32_t b0l = vtlo[nrow*VSTR + kb2h + (lane & 3)];
                    uint32_t b1l = vtlo[nrow*VSTR + kb2h + 4 + (lane & 3)];
                    mma16816(oacc[mi][d], pa, b0h, b1h);
                    mma16816(oacc[mi][d], pa, b0l, b1l);
                    mma16816(oacc[mi][d], pl, b0h, b1h);
                }
            }
        }
    }

    #pragma unroll
    for (int mi = 0; mi < 2; mi++) {
        float iA = 1.f / lrun[mi][0], iB = 1.f / lrun[mi][1];
        int rA = w*32 + mi*16 + (lane >> 2), rB = rA + 8;
        #pragma unroll
        for (int d = 0; d < 2; d++) {
            *(float2*)(out + base + (size_t)rA*rstr + d*8 + c2) =
                make_float2(oacc[mi][d][0]*iA, oacc[mi][d][1]*iA);
            *(float2*)(out + base + (size_t)rB*rstr + d*8 + c2) =
                make_float2(oacc[mi][d][2]*iB, oacc[mi][d][3]*iB);
        }
    }
}

// ---------------- launch ---------------------------------------------------
extern "C" void kernel_launch(void* const* d_in, const int* in_sizes, int n_in,
                              void* d_out, int out_size) {
    const float* x       = (const float*)d_in[0];
    const float* adjlog  = (const float*)d_in[1];
    const float* var_emb = (const float*)d_in[2];
    const float* temp_emb= (const float*)d_in[3];
    const float* mech_W  = (const float*)d_in[4];
    const float* mech_b  = (const float*)d_in[5];
    const float* ln_g    = (const float*)d_in[6];
    const float* ln_b    = (const float*)d_in[7];
    const float* Wq      = (const float*)d_in[8];
    const float* Wk      = (const float*)d_in[9];
    const float* Wv      = (const float*)d_in[10];
    const float* Wo      = (const float*)d_in[11];
    const float* bq      = (const float*)d_in[12];
    const float* bk      = (const float*)d_in[13];
    const float* bv      = (const float*)d_in[14];
    const float* bo      = (const float*)d_in[15];
    const float* out_W   = (const float*)d_in[16];
    const float* out_b   = (const float*)d_in[17];
    float* out = (float*)d_out;

    float *adjT, *z, *z2, *qkv;
    __nv_bfloat16 *whi, *wlo;
    cudaGetSymbolAddress((void**)&adjT, g_adjT);
    cudaGetSymbolAddress((void**)&z,    g_z);
    cudaGetSymbolAddress((void**)&z2,   g_z2);
    cudaGetSymbolAddress((void**)&qkv,  g_qkv);
    cudaGetSymbolAddress((void**)&whi,  g_whi);
    cudaGetSymbolAddress((void**)&wlo,  g_wlo);

    prep_adj_kernel<<<(V_*V_*LP1_ + 255)/256, 256>>>(adjlog, adjT);
    prep_w_kernel<<<dim3(4,4,7*V_), dim3(32,8)>>>(mech_W, Wq, Wk, Wv, Wo, whi, wlo);
    stage1_kernel<<<M_, 256>>>(x, adjT, var_emb, temp_emb, z);

    dim3 gg(M_/64, V_);
    fused_mech<<<gg, 128, FGSM>>>(z, mech_b, ln_g, ln_b, whi, wlo, z2);
    fused_qkv<<<gg, 128, FGSM>>>(z2, whi, wlo, qkv);
    attn_mma<<<B_*V_*NH_, 256>>>(qkv, bq, bk, bv, z);
    oproj_gemm<<<gg, 128, FGSM>>>(z, whi, wlo, bo, out_W, out_b, out);
}

// round 15
// speedup vs baseline: 1.2198x; 1.2198x over previous
#include <cuda_runtime.h>
#include <cuda_bf16.h>
#include <math.h>
#include <stdint.h>

#define B_   4
#define S_   256
#define V_   64
#define LP1_ 11
#define H_   128
#define NH_  8
#define DH_  16
#define NL_  3
#define M_   (B_*S_)   // 1024

// ---------------- scratch (device globals; no allocation) ----------------
__device__ float g_adjT[V_*LP1_*V_];
__device__ float g_z [M_*V_*H_];
__device__ float g_qkv[3*M_*V_*H_];
__device__ __align__(16) __nv_bfloat16 g_whi[7*V_*H_*H_];   // W^T[slot*64+v][n][k]
__device__ __align__(16) __nv_bfloat16 g_wlo[7*V_*H_*H_];

// ---------------- pack helpers --------------------------------------------
__device__ __forceinline__ uint32_t pkrn(float x, float y) {
    __nv_bfloat162 h = __floats2bfloat162_rn(x, y);
    return *(uint32_t*)&h;
}
__device__ __forceinline__ uint32_t pklo(float x, float y, uint32_t hi) {
    __nv_bfloat162 h = *(__nv_bfloat162*)&hi;
    return pkrn(x - __bfloat162float(h.x), y - __bfloat162float(h.y));
}
__device__ __forceinline__ void pack_trunc2(float a, float b, uint32_t& h, uint32_t& l) {
    uint32_t ba = __float_as_uint(a), bb = __float_as_uint(b);
    h = __byte_perm(ba, bb, 0x7632);
    float ra = a - __uint_as_float(ba & 0xFFFF0000u);
    float rb = b - __uint_as_float(bb & 0xFFFF0000u);
    l = __byte_perm(__float_as_uint(ra), __float_as_uint(rb), 0x7632);
}

__device__ __forceinline__ uint32_t smem_u32(const void* p) {
    uint32_t a;
    asm("{ .reg .u64 t; cvta.to.shared.u64 t, %1; cvt.u32.u64 %0, t; }" : "=r"(a) : "l"(p));
    return a;
}
__device__ __forceinline__ void cpa16(uint32_t dst, const void* src) {
    asm volatile("cp.async.ca.shared.global [%0], [%1], 16;" :: "r"(dst), "l"(src));
}
#define CP_COMMIT() asm volatile("cp.async.commit_group;" ::: "memory")
#define CP_WAIT(n)  asm volatile("cp.async.wait_group %0;" :: "n"(n) : "memory")

__device__ __forceinline__ void mma16816(float* c, const uint32_t* a, uint32_t b0, uint32_t b1) {
    asm volatile(
        "mma.sync.aligned.m16n8k16.row.col.f32.bf16.bf16.f32 "
        "{%0,%1,%2,%3}, {%4,%5,%6,%7}, {%8,%9}, {%0,%1,%2,%3};\n"
        : "+f"(c[0]), "+f"(c[1]), "+f"(c[2]), "+f"(c[3])
        : "r"(a[0]), "r"(a[1]), "r"(a[2]), "r"(a[3]), "r"(b0), "r"(b1));
}
__device__ __forceinline__ void ldsm4(uint32_t* r, uint32_t addr) {
    asm volatile("ldmatrix.sync.aligned.m8n8.x4.shared.b16 {%0,%1,%2,%3}, [%4];"
        : "=r"(r[0]), "=r"(r[1]), "=r"(r[2]), "=r"(r[3]) : "r"(addr));
}

// ---------------- stage 0: sigmoid + transpose of adjacency --------------
__global__ void prep_adj_kernel(const float* __restrict__ logits, float* __restrict__ adjT) {
    int idx = blockIdx.x * 256 + threadIdx.x;
    if (idx >= V_*V_*LP1_) return;
    int s = idx % V_;
    int r = idx / V_;
    int l = r % LP1_;
    int i = r / LP1_;
    float x = logits[(s*V_ + i)*LP1_ + l];
    adjT[idx] = 1.f / (1.f + __expf(-x));
}

// ------- weight transpose+split: wt[slot*64+v][n][k] = W[..][k][n] --------
__global__ void prep_w_kernel(const float* __restrict__ mW,
                              const float* __restrict__ Wq, const float* __restrict__ Wk,
                              const float* __restrict__ Wv, const float* __restrict__ Wo,
                              __nv_bfloat16* __restrict__ whi, __nv_bfloat16* __restrict__ wlo) {
    int sv = blockIdx.z;
    int s = sv >> 6, v = sv & 63;
    const float* src;
    if (s < 3)       src = mW + ((size_t)(v*NL_ + s))*H_*H_;
    else if (s == 3) src = Wq + (size_t)v*H_*H_;
    else if (s == 4) src = Wk + (size_t)v*H_*H_;
    else if (s == 5) src = Wv + (size_t)v*H_*H_;
    else             src = Wo + (size_t)v*H_*H_;
    __shared__ float t[32][33];
    int nbase = blockIdx.x*32, kbase = blockIdx.y*32;
    int tx = threadIdx.x, ty = threadIdx.y;
    #pragma unroll
    for (int j = 0; j < 4; j++)
        t[ty + j*8][tx] = src[(size_t)(kbase + ty + j*8)*H_ + nbase + tx];
    __syncthreads();
    size_t obase = (size_t)sv*H_*H_;
    #pragma unroll
    for (int j = 0; j < 4; j++) {
        int n = nbase + ty + j*8;
        int k = kbase + tx;
        float f = t[tx][ty + j*8];
        __nv_bfloat16 hb = __float2bfloat16(f);
        float rl = f - __bfloat162float(hb);
        __nv_bfloat16 lb = __float2bfloat16(rl);
        whi[obase + (size_t)n*H_ + k] = hb;
        wlo[obase + (size_t)n*H_ + k] = lb;
    }
}

// ---------------- stage 1: z[b,t,i,h] -------------------------------------
__global__ __launch_bounds__(256)
void stage1_kernel(const float* __restrict__ x, const float* __restrict__ adjT,
                   const float* __restrict__ var_emb, const float* __restrict__ temp_emb,
                   float* __restrict__ z) {
    int bt = blockIdx.x;
    int b = bt >> 8;
    int t = bt & 255;
    __shared__ float xw[LP1_][V_];
    __shared__ float Am[V_][V_ + 1];
    __shared__ float Bls[V_][LP1_ + 1];
    int tid = threadIdx.x;

    for (int p = tid; p < LP1_*V_; p += 256) {
        int l = p / V_, s = p % V_;
        int tt = t - l;
        xw[l][s] = (tt >= 0) ? x[((size_t)(b*S_ + tt))*V_ + s] : 0.f;
    }
    __syncthreads();

    for (int p = tid; p < V_*V_; p += 256) {
        int i = p >> 6, s = p & 63;
        const float* ap = adjT + (size_t)i*LP1_*V_ + s;
        float a = 0.f;
        #pragma unroll
        for (int l = 0; l < LP1_; l++) a += xw[l][s] * ap[l*V_];
        Am[i][s] = a;
    }
    for (int p = tid; p < V_*LP1_; p += 256) {
        int i = p / LP1_, l = p % LP1_;
        const float* ap = adjT + ((size_t)i*LP1_ + l)*V_;
        float a = 0.f;
        #pragma unroll 8
        for (int s = 0; s < V_; s++) a += xw[l][s] * ap[s];
        Bls[i][l] = a;
    }
    __syncthreads();

    int tx = tid & 15, ty = tid >> 4;
    float acc[4][8];
    #pragma unroll
    for (int r = 0; r < 4; r++)
        #pragma unroll
        for (int c = 0; c < 8; c++) acc[r][c] = 0.f;

    for (int s = 0; s < V_; s++) {
        float a0 = Am[ty*4+0][s], a1 = Am[ty*4+1][s], a2 = Am[ty*4+2][s], a3 = Am[ty*4+3][s];
        const float4* vp = (const float4*)(var_emb + (size_t)s*H_ + tx*8);
        float4 v0 = vp[0], v1 = vp[1];
        float bv[8] = {v0.x,v0.y,v0.z,v0.w,v1.x,v1.y,v1.z,v1.w};
        #pragma unroll
        for (int c = 0; c < 8; c++) {
            acc[0][c] += a0*bv[c]; acc[1][c] += a1*bv[c];
            acc[2][c] += a2*bv[c]; acc[3][c] += a3*bv[c];
        }
    }
    #pragma unroll
    for (int l = 0; l < LP1_; l++) {
        float a0 = Bls[ty*4+0][l], a1 = Bls[ty*4+1][l], a2 = Bls[ty*4+2][l], a3 = Bls[ty*4+3][l];
        const float4* vp = (const float4*)(temp_emb + (size_t)l*H_ + tx*8);
        float4 v0 = vp[0], v1 = vp[1];
        float bv[8] = {v0.x,v0.y,v0.z,v0.w,v1.x,v1.y,v1.z,v1.w};
        #pragma unroll
        for (int c = 0; c < 8; c++) {
            acc[0][c] += a0*bv[c]; acc[1][c] += a1*bv[c];
            acc[2][c] += a2*bv[c]; acc[3][c] += a3*bv[c];
        }
    }
    #pragma unroll
    for (int r = 0; r < 4; r++) {
        int i = ty*4 + r;
        float* zp = z + ((size_t)bt*V_ + i)*H_ + tx*8;
        *(float4*)(zp)   = make_float4(acc[r][0], acc[r][1], acc[r][2], acc[r][3]);
        *(float4*)(zp+4) = make_float4(acc[r][4], acc[r][5], acc[r][6], acc[r][7]);
    }
}

// ========= raw-mma GEMM chain: BM=64, 8 warps (warp = 32 rows x 32 cols) ===
// smem: par 4608 | rowred 4096 | A hi 17408 | A lo 17408 | W ring 2x20480
#define FP_PAR 0
#define RED    4608
#define FSA_HI 8704
#define FSA_LO (FSA_HI + 17408)
#define FSB0   (FSA_LO + 17408)       // 43520
#define WBUF   20480                  // hi 10240 | lo 10240
#define FSB1   (FSB0 + WBUF)          // 64000
#define FGSM   (FSB1 + WBUF)          // 84480
#define WSHALF 10240
#define PW     20                     // u32 words per n-row (conflict-free)
#define LD2    136                    // bf16 elems per A smem row

// A tile fill: 64 rows x 128 cols fp32 -> bf16 hi/lo smem (truncation split)
__device__ __forceinline__ void fillA(char* smem, const float* __restrict__ src,
                                      size_t rstr, int tid) {
    __nv_bfloat16* aH = (__nv_bfloat16*)(smem + FSA_HI);
    __nv_bfloat16* aL = (__nv_bfloat16*)(smem + FSA_LO);
    #pragma unroll
    for (int i = 0; i < 8; i++) {
        int f = tid + 256*i;
        int row = f >> 5, c4 = f & 31;
        float4 vv = *(const float4*)(src + (size_t)row*rstr + c4*4);
        uint32_t h0, l0, h1, l1;
        pack_trunc2(vv.x, vv.y, h0, l0);
        pack_trunc2(vv.z, vv.w, h1, l1);
        int off = row*LD2 + c4*4;
        *(uint2*)(aH + off) = make_uint2(h0, h1);
        *(uint2*)(aL + off) = make_uint2(l0, l1);
    }
}

// cp.async one 32-k chunk of W^T (hi+lo): 512 jobs over 256 threads
__device__ __forceinline__ void stageW(uint32_t sb, const __nv_bfloat16* __restrict__ hi,
                                       const __nv_bfloat16* __restrict__ lo,
                                       int chunk, int tid) {
    #pragma unroll
    for (int i = 0; i < 2; i++) {
        int f = tid + 256*i;
        int n = f >> 2, seg = f & 3;
        uint32_t so = (uint32_t)n*(PW*4) + seg*16;
        size_t go = (size_t)n*H_ + chunk*32 + seg*8;
        cpa16(sb + so, hi + go);
        cpa16(sb + WSHALF + so, lo + go);
    }
}

// mma over one 32-k chunk from W buffer sb
__device__ __forceinline__ void mma_chunk(char* smem, uint32_t sbase, int sb, int c,
                                          int wm, int wn, int lane,
                                          float (&acc)[2][4][4]) {
    const uint32_t* ws  = (const uint32_t*)(smem + sb);
    const uint32_t* wsl = (const uint32_t*)(smem + sb + WSHALF);
    uint32_t arow = (uint32_t)(wm*32 + (lane & 15));
    uint32_t acol16 = (uint32_t)((lane >> 4) * 8);
    #pragma unroll
    for (int ks = 0; ks < 2; ks++) {
        int kofs = c*32 + ks*16;
        uint32_t ah[2][4], al[2][4];
        #pragma unroll
        for (int mi = 0; mi < 2; mi++) {
            uint32_t off = ((arow + mi*16)*LD2 + kofs + acol16) * 2;
            ldsm4(ah[mi], sbase + FSA_HI + off);
            ldsm4(al[mi], sbase + FSA_LO + off);
        }
        int wb = (wn*32 + (lane >> 2))*PW + ks*8 + (lane & 3);
        #pragma unroll
        for (int nj = 0; nj < 4; nj++) {
            int wi = wb + nj*8*PW;
            uint32_t b0h = ws[wi],  b1h = ws[wi+4];
            uint32_t b0l = wsl[wi], b1l = wsl[wi+4];
            #pragma unroll
            for (int mi = 0; mi < 2; mi++) {
                mma16816(acc[mi][nj], ah[mi], b0h, b1h);
                mma16816(acc[mi][nj], ah[mi], b0l, b1l);
                mma16816(acc[mi][nj], al[mi], b0h, b1h);
            }
        }
    }
}

// run 4 chunks of one layer with cross-layer prefetch.
// entry invariant: chunks (cur,0),(cur,1) already committed (2 groups pending).
__device__ __forceinline__ void layer_chunks(char* smem, uint32_t sbase,
        const __nv_bfloat16* curH, const __nv_bfloat16* curL,
        const __nv_bfloat16* nxtH, const __nv_bfloat16* nxtL, bool has_next,
        int tid, int wm, int wn, int lane, float (&acc)[2][4][4]) {
    #pragma unroll
    for (int mi = 0; mi < 2; mi++)
        #pragma unroll
        for (int nj = 0; nj < 4; nj++)
            #pragma unroll
            for (int e = 0; e < 4; e++) acc[mi][nj][e] = 0.f;
    const int bufs[2] = {FSB0, FSB1};
    #pragma unroll
    for (int c = 0; c < 4; c++) {
        if (c == 3 && !has_next) { CP_WAIT(0); } else { CP_WAIT(1); }
        __syncthreads();
        mma_chunk(smem, sbase, bufs[c&1], c, wm, wn, lane, acc);
        __syncthreads();
        if (c < 2) {
            stageW(sbase + bufs[c&1], curH, curL, c+2, tid);
            CP_COMMIT();
        } else if (has_next) {
            stageW(sbase + bufs[c&1], nxtH, nxtL, c-2, tid);
            CP_COMMIT();
        }
    }
}

// ---------------- fused 6-layer chain: 3 mech + QKV ------------------------
__global__ __launch_bounds__(256, 2)
void fused_chain(const float* __restrict__ z, const float* __restrict__ mech_b,
                 const float* __restrict__ lng, const float* __restrict__ lnb,
                 const __nv_bfloat16* __restrict__ whi, const __nv_bfloat16* __restrict__ wlo,
                 float* __restrict__ qkv) {
    extern __shared__ char smem[];
    uint32_t sbase = smem_u32(smem);
    int tid = threadIdx.x, w = tid >> 5, lane = tid & 31;
    int wm = w & 1, wn = w >> 1;
    int v = blockIdx.y, m0 = blockIdx.x * 64;
    int qd = lane >> 2, mq = lane & 3;

    float* sBias = (float*)(smem + FP_PAR);
    float* sG    = sBias + 384;
    float* sBeta = sG + 384;
    float* rsum  = (float*)(smem + RED);
    float* rsq   = (float*)(smem + RED + 2048);
    if (tid < 128) {
        #pragma unroll
        for (int li = 0; li < 3; li++) {
            sBias[li*128 + tid] = mech_b[(size_t)v*NL_*H_ + li*H_ + tid];
            sG[li*128 + tid]    = lng  [(size_t)v*NL_*H_ + li*H_ + tid];
            sBeta[li*128 + tid] = lnb  [(size_t)v*NL_*H_ + li*H_ + tid];
        }
    }

    size_t slot = (size_t)V_*H_*H_;
    size_t wofs = (size_t)v*H_*H_;
    // prefetch layer0 chunks 0,1 first, then convert A (overlap)
    stageW(sbase + FSB0, whi + wofs, wlo + wofs, 0, tid);
    CP_COMMIT();
    stageW(sbase + FSB1, whi + wofs, wlo + wofs, 1, tid);
    CP_COMMIT();
    fillA(smem, z + ((size_t)m0*V_ + v)*H_, (size_t)V_*H_, tid);

    __nv_bfloat16* aH = (__nv_bfloat16*)(smem + FSA_HI);
    __nv_bfloat16* aL = (__nv_bfloat16*)(smem + FSA_LO);
    float acc[2][4][4];

    #pragma unroll
    for (int li = 0; li < 6; li++) {
        const __nv_bfloat16* curH = whi + (size_t)li*slot + wofs;
        const __nv_bfloat16* curL = wlo + (size_t)li*slot + wofs;
        const __nv_bfloat16* nxtH = whi + (size_t)(li+1)*slot + wofs;
        const __nv_bfloat16* nxtL = wlo + (size_t)(li+1)*slot + wofs;
        layer_chunks(smem, sbase, curH, curL, nxtH, nxtL, li < 5,
                     tid, wm, wn, lane, acc);

        if (li < 3) {
            // ---- LN + GELU epilogue in registers ----
            float bb[4][2];
            #pragma unroll
            for (int nj = 0; nj < 4; nj++) {
                float2 b2 = *(const float2*)(sBias + li*128 + wn*32 + nj*8 + mq*2);
                bb[nj][0] = b2.x; bb[nj][1] = b2.y;
            }
            float s[2][2], q[2][2];
            #pragma unroll
            for (int mi = 0; mi < 2; mi++) {
                s[mi][0]=0.f; s[mi][1]=0.f; q[mi][0]=0.f; q[mi][1]=0.f;
                #pragma unroll
                for (int nj = 0; nj < 4; nj++) {
                    float y0 = acc[mi][nj][0] + bb[nj][0];
                    float y1 = acc[mi][nj][1] + bb[nj][1];
                    float y2 = acc[mi][nj][2] + bb[nj][0];
                    float y3 = acc[mi][nj][3] + bb[nj][1];
                    acc[mi][nj][0]=y0; acc[mi][nj][1]=y1; acc[mi][nj][2]=y2; acc[mi][nj][3]=y3;
                    s[mi][0] += y0+y1; q[mi][0] += y0*y0+y1*y1;
                    s[mi][1] += y2+y3; q[mi][1] += y2*y2+y3*y3;
                }
                #pragma unroll
                for (int h = 0; h < 2; h++) {
                    s[mi][h] += __shfl_xor_sync(0xFFFFFFFFu, s[mi][h], 1);
                    q[mi][h] += __shfl_xor_sync(0xFFFFFFFFu, q[mi][h], 1);
                    s[mi][h] += __shfl_xor_sync(0xFFFFFFFFu, s[mi][h], 2);
                    q[mi][h] += __shfl_xor_sync(0xFFFFFFFFu, q[mi][h], 2);
                }
            }
            if (mq == 0) {
                #pragma unroll
                for (int mi = 0; mi < 2; mi++) {
                    int r0 = wm*32 + mi*16 + qd;
                    rsum[r0*4 + wn]     = s[mi][0];
                    rsq [r0*4 + wn]     = q[mi][0];
                    rsum[(r0+8)*4 + wn] = s[mi][1];
                    rsq [(r0+8)*4 + wn] = q[mi][1];
                }
            }
            __syncthreads();
            float gg[4][2], lb[4][2];
            #pragma unroll
            for (int nj = 0; nj < 4; nj++) {
                float2 g2 = *(const float2*)(sG + li*128 + wn*32 + nj*8 + mq*2);
                float2 l2 = *(const float2*)(sBeta + li*128 + wn*32 + nj*8 + mq*2);
                gg[nj][0]=g2.x; gg[nj][1]=g2.y; lb[nj][0]=l2.x; lb[nj][1]=l2.y;
            }
            #pragma unroll
            for (int mi = 0; mi < 2; mi++) {
                int r0 = wm*32 + mi*16 + qd;
                float4 s4a = *(const float4*)(rsum + r0*4);
                float4 q4a = *(const float4*)(rsq + r0*4);
                float4 s4b = *(const float4*)(rsum + (r0+8)*4);
                float4 q4b = *(const float4*)(rsq + (r0+8)*4);
                float sm0 = s4a.x+s4a.y+s4a.z+s4a.w, sq0 = q4a.x+q4a.y+q4a.z+q4a.w;
                float sm1 = s4b.x+s4b.y+s4b.z+s4b.w, sq1 = q4b.x+q4b.y+q4b.z+q4b.w;
                float mean0 = sm0*(1.f/128.f), var0 = sq0*(1.f/128.f) - mean0*mean0;
                float mean1 = sm1*(1.f/128.f), var1 = sq1*(1.f/128.f) - mean1*mean1;
                float rs0 = rsqrtf(var0 + 1e-5f), rs1 = rsqrtf(var1 + 1e-5f);
                #pragma unroll
                for (int nj = 0; nj < 4; nj++) {
                    float t0 = (acc[mi][nj][0]-mean0)*rs0*gg[nj][0] + lb[nj][0];
                    float t1 = (acc[mi][nj][1]-mean0)*rs0*gg[nj][1] + lb[nj][1];
                    float t2 = (acc[mi][nj][2]-mean1)*rs1*gg[nj][0] + lb[nj][0];
                    float t3 = (acc[mi][nj][3]-mean1)*rs1*gg[nj][1] + lb[nj][1];
                    t0 = 0.5f*t0*(1.f + erff(t0*0.7071067811865476f));
                    t1 = 0.5f*t1*(1.f + erff(t1*0.7071067811865476f));
                    t2 = 0.5f*t2*(1.f + erff(t2*0.7071067811865476f));
                    t3 = 0.5f*t3*(1.f + erff(t3*0.7071067811865476f));
                    int col = wn*32 + nj*8 + mq*2;
                    uint32_t h0, l0, h1, l1;
                    pack_trunc2(t0, t1, h0, l0);
                    pack_trunc2(t2, t3, h1, l1);
                    int oa = r0*LD2 + col;
                    int ob = (r0+8)*LD2 + col;
                    *(uint32_t*)(aH + oa) = h0;  *(uint32_t*)(aL + oa) = l0;
                    *(uint32_t*)(aH + ob) = h1;  *(uint32_t*)(aL + ob) = l1;
                }
            }
            __syncthreads();   // A writes + rowred reuse ordered before next use
        } else {
            // ---- QKV: store fragments straight to gmem ----
            float* o = qkv + (size_t)(li-3)*M_*V_*H_;
            #pragma unroll
            for (int mi = 0; mi < 2; mi++) {
                int r0 = m0 + wm*32 + mi*16 + qd;
                #pragma unroll
                for (int nj = 0; nj < 4; nj++) {
                    int col = wn*32 + nj*8 + mq*2;
                    *(float2*)(o + ((size_t)r0*V_ + v)*H_ + col) =
                        make_float2(acc[mi][nj][0], acc[mi][nj][1]);
                    *(float2*)(o + ((size_t)(r0+8)*V_ + v)*H_ + col) =
                        make_float2(acc[mi][nj][2], acc[mi][nj][3]);
                }
            }
        }
    }
}

// ---------------- O-proj + output head -------------------------------------
__global__ __launch_bounds__(256, 2)
void oproj_gemm(const float* __restrict__ att,
                const __nv_bfloat16* __restrict__ whi, const __nv_bfloat16* __restrict__ wlo,
                const float* __restrict__ bo, const float* __restrict__ oW,
                const float* __restrict__ oB, float* __restrict__ out) {
    extern __shared__ char smem[];
    uint32_t sbase = smem_u32(smem);
    int tid = threadIdx.x, w = tid >> 5, lane = tid & 31;
    int wm = w & 1, wn = w >> 1;
    int v = blockIdx.y, m0 = blockIdx.x * 64;
    int qd = lane >> 2, mq = lane & 3;

    float* sBias = (float*)(smem + FP_PAR);
    float* sG    = sBias + 384;
    float* rsum  = (float*)(smem + RED);
    if (tid < 128) {
        sBias[tid] = bo[(size_t)v*H_ + tid];
        sG[tid]    = oW[(size_t)v*H_ + tid];
    }
    size_t wofs = (size_t)6*V_*H_*H_ + (size_t)v*H_*H_;
    stageW(sbase + FSB0, whi + wofs, wlo + wofs, 0, tid);
    CP_COMMIT();
    stageW(sbase + FSB1, whi + wofs, wlo + wofs, 1, tid);
    CP_COMMIT();
    fillA(smem, att + ((size_t)m0*V_ + v)*H_, (size_t)V_*H_, tid);

    float acc[2][4][4];
    layer_chunks(smem, sbase, whi + wofs, wlo + wofs, nullptr, nullptr, false,
                 tid, wm, wn, lane, acc);

    float p[2][2];
    #pragma unroll
    for (int mi = 0; mi < 2; mi++) {
        p[mi][0] = 0.f; p[mi][1] = 0.f;
        #pragma unroll
        for (int nj = 0; nj < 4; nj++) {
            int col = wn*32 + nj*8 + mq*2;
            float2 b2 = *(const float2*)(sBias + col);
            float2 g2 = *(const float2*)(sG + col);
            p[mi][0] += (acc[mi][nj][0]+b2.x)*g2.x + (acc[mi][nj][1]+b2.y)*g2.y;
            p[mi][1] += (acc[mi][nj][2]+b2.x)*g2.x + (acc[mi][nj][3]+b2.y)*g2.y;
        }
        #pragma unroll
        for (int h = 0; h < 2; h++) {
            p[mi][h] += __shfl_xor_sync(0xFFFFFFFFu, p[mi][h], 1);
            p[mi][h] += __shfl_xor_sync(0xFFFFFFFFu, p[mi][h], 2);
        }
    }
    if (mq == 0) {
        #pragma unroll
        for (int mi = 0; mi < 2; mi++) {
            int r0 = wm*32 + mi*16 + qd;
            rsum[r0*4 + wn]     = p[mi][0];
            rsum[(r0+8)*4 + wn] = p[mi][1];
        }
    }
    __syncthreads();
    if (wn == 0 && mq == 0) {
        float ob = oB[v];
        #pragma unroll
        for (int mi = 0; mi < 2; mi++) {
            int r0 = wm*32 + mi*16 + qd;
            float4 a4 = *(const float4*)(rsum + r0*4);
            float4 b4 = *(const float4*)(rsum + (r0+8)*4);
            out[(size_t)(m0+r0)*V_ + v]   = a4.x+a4.y+a4.z+a4.w + ob;
            out[(size_t)(m0+r0+8)*V_ + v] = b4.x+b4.y+b4.z+b4.w + ob;
        }
    }
}

// ================= flash-style mma attention ===============================
#define KSTR 12
#define VSTR 132

__global__ __launch_bounds__(256)
void attn_mma(const float* __restrict__ qkv,
              const float* __restrict__ bq, const float* __restrict__ bk,
              const float* __restrict__ bv, float* __restrict__ out) {
    __shared__ uint32_t khi[256*KSTR], klo[256*KSTR];
    __shared__ uint32_t vthi[16*VSTR], vtlo[16*VSTR];

    int bid = blockIdx.x;
    int n = bid & 7, v = (bid >> 3) & 63, b = bid >> 9;
    int tid = threadIdx.x, w = tid >> 5, lane = tid & 31;

    const float* q  = qkv;
    const float* kk = qkv + (size_t)M_*V_*H_;
    const float* vv = qkv + 2*(size_t)M_*V_*H_;
    size_t rstr = (size_t)V_*H_;
    size_t base = ((size_t)(b*S_)*V_ + v)*H_ + n*DH_;
    size_t bofs = (size_t)v*H_ + n*DH_;

    {
        int key = tid;
        const float4* kp = (const float4*)(kk + base + (size_t)key*rstr);
        const float4* vp = (const float4*)(vv + base + (size_t)key*rstr);
        float kr[16], vr[16];
        #pragma unroll
        for (int i = 0; i < 4; i++) {
            float4 a = kp[i], c = vp[i];
            float4 bb = *(const float4*)(bk + bofs + i*4);
            float4 cb = *(const float4*)(bv + bofs + i*4);
            kr[i*4+0]=a.x+bb.x; kr[i*4+1]=a.y+bb.y; kr[i*4+2]=a.z+bb.z; kr[i*4+3]=a.w+bb.w;
            vr[i*4+0]=c.x+cb.x; vr[i*4+1]=c.y+cb.y; vr[i*4+2]=c.z+cb.z; vr[i*4+3]=c.w+cb.w;
        }
        #pragma unroll
        for (int d = 0; d < 8; d++) {
            uint32_t h = pkrn(kr[2*d], kr[2*d+1]);
            khi[key*KSTR + d] = h;
            klo[key*KSTR + d] = pklo(kr[2*d], kr[2*d+1], h);
        }
        unsigned short* vthi16 = (unsigned short*)vthi;
        unsigned short* vtlo16 = (unsigned short*)vtlo;
        #pragma unroll
        for (int c = 0; c < 16; c++) {
            __nv_bfloat16 hb = __float2bfloat16(vr[c]);
            float lo = vr[c] - __bfloat162float(hb);
            __nv_bfloat16 lb = __float2bfloat16(lo);
            vthi16[c*(2*VSTR) + key] = __bfloat16_as_ushort(hb);
            vtlo16[c*(2*VSTR) + key] = __bfloat16_as_ushort(lb);
        }
    }

    int rq = w*32 + (lane >> 2);
    int c2 = (lane & 3) * 2;
    float2 bq0 = make_float2(bq[bofs + c2],     bq[bofs + c2 + 1]);
    float2 bq1 = make_float2(bq[bofs + c2 + 8], bq[bofs + c2 + 9]);
    uint32_t qhi[2][4], qlo[2][4];
    #pragma unroll
    for (int mi = 0; mi < 2; mi++) {
        int rA = rq + mi*16, rB = rA + 8;
        float2 x00 = *(const float2*)(q + base + (size_t)rA*rstr + c2);
        float2 x01 = *(const float2*)(q + base + (size_t)rA*rstr + c2 + 8);
        float2 x10 = *(const float2*)(q + base + (size_t)rB*rstr + c2);
        float2 x11 = *(const float2*)(q + base + (size_t)rB*rstr + c2 + 8);
        x00.x = (x00.x + bq0.x)*0.25f; x00.y = (x00.y + bq0.y)*0.25f;
        x01.x = (x01.x + bq1.x)*0.25f; x01.y = (x01.y + bq1.y)*0.25f;
        x10.x = (x10.x + bq0.x)*0.25f; x10.y = (x10.y + bq0.y)*0.25f;
        x11.x = (x11.x + bq1.x)*0.25f; x11.y = (x11.y + bq1.y)*0.25f;
        qhi[mi][0] = pkrn(x00.x, x00.y); qlo[mi][0] = pklo(x00.x, x00.y, qhi[mi][0]);
        qhi[mi][1] = pkrn(x10.x, x10.y); qlo[mi][1] = pklo(x10.x, x10.y, qhi[mi][1]);
        qhi[mi][2] = pkrn(x01.x, x01.y); qlo[mi][2] = pklo(x01.x, x01.y, qhi[mi][2]);
        qhi[mi][3] = pkrn(x11.x, x11.y); qlo[mi][3] = pklo(x11.x, x11.y, qhi[mi][3]);
    }
    __syncthreads();

    float oacc[2][2][4];
    #pragma unroll
    for (int mi = 0; mi < 2; mi++)
        #pragma unroll
        for (int d = 0; d < 2; d++)
            #pragma unroll
            for (int e = 0; e < 4; e++) oacc[mi][d][e] = 0.f;
    float mrun[2][2] = {{-1e30f,-1e30f},{-1e30f,-1e30f}};
    float lrun[2][2] = {{0.f,0.f},{0.f,0.f}};

    #pragma unroll
    for (int kt = 0; kt < 4; kt++) {
        int kb = kt * 64;
        uint32_t sbh[8][2], sbl[8][2];
        #pragma unroll
        for (int j = 0; j < 8; j++) {
            int key = kb + j*8 + (lane >> 2);
            int ci  = lane & 3;
            sbh[j][0] = khi[key*KSTR + ci];     sbh[j][1] = khi[key*KSTR + ci + 4];
            sbl[j][0] = klo[key*KSTR + ci];     sbl[j][1] = klo[key*KSTR + ci + 4];
        }
        #pragma unroll
        for (int mi = 0; mi < 2; mi++) {
            float C[8][4];
            #pragma unroll
            for (int j = 0; j < 8; j++) { C[j][0]=0.f; C[j][1]=0.f; C[j][2]=0.f; C[j][3]=0.f; }
            #pragma unroll
            for (int j = 0; j < 8; j++) {
                mma16816(C[j], qhi[mi], sbh[j][0], sbh[j][1]);
                mma16816(C[j], qhi[mi], sbl[j][0], sbl[j][1]);
                mma16816(C[j], qlo[mi], sbh[j][0], sbh[j][1]);
            }
            float mA = -1e30f, mB = -1e30f;
            #pragma unroll
            for (int j = 0; j < 8; j++) {
                mA = fmaxf(mA, fmaxf(C[j][0], C[j][1]));
                mB = fmaxf(mB, fmaxf(C[j][2], C[j][3]));
            }
            mA = fmaxf(mA, __shfl_xor_sync(0xFFFFFFFFu, mA, 1));
            mA = fmaxf(mA, __shfl_xor_sync(0xFFFFFFFFu, mA, 2));
            mB = fmaxf(mB, __shfl_xor_sync(0xFFFFFFFFu, mB, 1));
            mB = fmaxf(mB, __shfl_xor_sync(0xFFFFFFFFu, mB, 2));
            float nA = fmaxf(mrun[mi][0], mA), nB = fmaxf(mrun[mi][1], mB);
            float cA = __expf(mrun[mi][0] - nA), cB = __expf(mrun[mi][1] - nB);
            mrun[mi][0] = nA; mrun[mi][1] = nB;
            float sA = 0.f, sB = 0.f;
            #pragma unroll
            for (int j = 0; j < 8; j++) {
                C[j][0] = __expf(C[j][0] - nA); C[j][1] = __expf(C[j][1] - nA);
                C[j][2] = __expf(C[j][2] - nB); C[j][3] = __expf(C[j][3] - nB);
                sA += C[j][0] + C[j][1];
                sB += C[j][2] + C[j][3];
            }
            sA += __shfl_xor_sync(0xFFFFFFFFu, sA, 1);
            sA += __shfl_xor_sync(0xFFFFFFFFu, sA, 2);
            sB += __shfl_xor_sync(0xFFFFFFFFu, sB, 1);
            sB += __shfl_xor_sync(0xFFFFFFFFu, sB, 2);
            lrun[mi][0] = lrun[mi][0]*cA + sA;
            lrun[mi][1] = lrun[mi][1]*cB + sB;
            #pragma unroll
            for (int d = 0; d < 2; d++) {
                oacc[mi][d][0] *= cA; oacc[mi][d][1] *= cA;
                oacc[mi][d][2] *= cB; oacc[mi][d][3] *= cB;
            }
            #pragma unroll
            for (int u = 0; u < 4; u++) {
                uint32_t pa[4], pl[4];
                pa[0] = pkrn(C[2*u][0],   C[2*u][1]);   pl[0] = pklo(C[2*u][0],   C[2*u][1],   pa[0]);
                pa[1] = pkrn(C[2*u][2],   C[2*u][3]);   pl[1] = pklo(C[2*u][2],   C[2*u][3],   pa[1]);
                pa[2] = pkrn(C[2*u+1][0], C[2*u+1][1]); pl[2] = pklo(C[2*u+1][0], C[2*u+1][1], pa[2]);
                pa[3] = pkrn(C[2*u+1][2], C[2*u+1][3]); pl[3] = pklo(C[2*u+1][2], C[2*u+1][3], pa[3]);
                int kb2h = (kb + u*16) >> 1;
                #pragma unroll
                for (int d = 0; d < 2; d++) {
                    int nrow = d*8 + (lane >> 2);
                    uint32_t b0h = vthi[nrow*VSTR + kb2h + (lane & 3)];
                    uint32_t b1h = vthi[nrow*VSTR + kb2h + 4 + (lane & 3)];
                    uint32_t b0l = vtlo[nrow*VSTR + kb2h + (lane & 3)];
                    uint32_t b1l = vtlo[nrow*VSTR + kb2h + 4 + (lane & 3)];
                    mma16816(oacc[mi][d], pa, b0h, b1h);
                    mma16816(oacc[mi][d], pa, b0l, b1l);
                    mma16816(oacc[mi][d], pl, b0h, b1h);
                }
            }
        }
    }

    #pragma unroll
    for (int mi = 0; mi < 2; mi++) {
        float iA = 1.f / lrun[mi][0], iB = 1.f / lrun[mi][1];
        int rA = w*32 + mi*16 + (lane >> 2), rB = rA + 8;
        #pragma unroll
        for (int d = 0; d < 2; d++) {
            *(float2*)(out + base + (size_t)rA*rstr + d*8 + c2) =
                make_float2(oacc[mi][d][0]*iA, oacc[mi][d][1]*iA);
            *(float2*)(out + base + (size_t)rB*rstr + d*8 + c2) =
                make_float2(oacc[mi][d][2]*iB, oacc[mi][d][3]*iB);
        }
    }
}

// ---------------- launch ---------------------------------------------------
extern "C" void kernel_launch(void* const* d_in, const int* in_sizes, int n_in,
                              void* d_out, int out_size) {
    const float* x       = (const float*)d_in[0];
    const float* adjlog  = (const float*)d_in[1];
    const float* var_emb = (const float*)d_in[2];
    const float* temp_emb= (const float*)d_in[3];
    const float* mech_W  = (const float*)d_in[4];
    const float* mech_b  = (const float*)d_in[5];
    const float* ln_g    = (const float*)d_in[6];
    const float* ln_b    = (const float*)d_in[7];
    const float* Wq      = (const float*)d_in[8];
    const float* Wk      = (const float*)d_in[9];
    const float* Wv      = (const float*)d_in[10];
    const float* Wo      = (const float*)d_in[11];
    const float* bq      = (const float*)d_in[12];
    const float* bk      = (const float*)d_in[13];
    const float* bv      = (const float*)d_in[14];
    const float* bo      = (const float*)d_in[15];
    const float* out_W   = (const float*)d_in[16];
    const float* out_b   = (const float*)d_in[17];
    float* out = (float*)d_out;

    float *adjT, *z, *qkv;
    __nv_bfloat16 *whi, *wlo;
    cudaGetSymbolAddress((void**)&adjT, g_adjT);
    cudaGetSymbolAddress((void**)&z,    g_z);
    cudaGetSymbolAddress((void**)&qkv,  g_qkv);
    cudaGetSymbolAddress((void**)&whi,  g_whi);
    cudaGetSymbolAddress((void**)&wlo,  g_wlo);

    cudaFuncSetAttribute(fused_chain, cudaFuncAttributeMaxDynamicSharedMemorySize, FGSM);
    cudaFuncSetAttribute(oproj_gemm,  cudaFuncAttributeMaxDynamicSharedMemorySize, FGSM);

    prep_adj_kernel<<<(V_*V_*LP1_ + 255)/256, 256>>>(adjlog, adjT);
    prep_w_kernel<<<dim3(4,4,7*V_), dim3(32,8)>>>(mech_W, Wq, Wk, Wv, Wo, whi, wlo);
    stage1_kernel<<<M_, 256>>>(x, adjT, var_emb, temp_emb, z);

    dim3 gg(M_/64, V_);
    fused_chain<<<gg, 256, FGSM>>>(z, mech_b, ln_g, ln_b, whi, wlo, qkv);
    attn_mma<<<B_*V_*NH_, 256>>>(qkv, bq, bk, bv, z);
    oproj_gemm<<<gg, 256, FGSM>>>(z, whi, wlo, bo, out_W, out_b, out);
}

// round 16
// speedup vs baseline: 1.3964x; 1.1448x over previous
#include <cuda_runtime.h>
#include <cuda_bf16.h>
#include <math.h>
#include <stdint.h>

#define B_   4
#define S_   256
#define V_   64
#define LP1_ 11
#define H_   128
#define NH_  8
#define DH_  16
#define NL_  3
#define M_   (B_*S_)   // 1024

// ---------------- scratch (device globals; no allocation) ----------------
__device__ float g_adjT[V_*LP1_*V_];
__device__ float g_z [M_*V_*H_];
__device__ float g_qkv[3*M_*V_*H_];
__device__ __align__(16) __nv_bfloat16 g_whi[7*V_*H_*H_];   // W^T[slot*64+v][n][k]
__device__ __align__(16) __nv_bfloat16 g_wlo[7*V_*H_*H_];
__device__ __align__(16) __nv_bfloat16 g_bembh[H_*80];      // Bemb^T[h][k], k=80
__device__ __align__(16) __nv_bfloat16 g_bembl[H_*80];

// ---------------- pack helpers --------------------------------------------
__device__ __forceinline__ uint32_t pkrn(float x, float y) {
    __nv_bfloat162 h = __floats2bfloat162_rn(x, y);
    return *(uint32_t*)&h;
}
__device__ __forceinline__ uint32_t pklo(float x, float y, uint32_t hi) {
    __nv_bfloat162 h = *(__nv_bfloat162*)&hi;
    return pkrn(x - __bfloat162float(h.x), y - __bfloat162float(h.y));
}
__device__ __forceinline__ void pack_trunc2(float a, float b, uint32_t& h, uint32_t& l) {
    uint32_t ba = __float_as_uint(a), bb = __float_as_uint(b);
    h = __byte_perm(ba, bb, 0x7632);
    float ra = a - __uint_as_float(ba & 0xFFFF0000u);
    float rb = b - __uint_as_float(bb & 0xFFFF0000u);
    l = __byte_perm(__float_as_uint(ra), __float_as_uint(rb), 0x7632);
}

__device__ __forceinline__ uint32_t smem_u32(const void* p) {
    uint32_t a;
    asm("{ .reg .u64 t; cvta.to.shared.u64 t, %1; cvt.u32.u64 %0, t; }" : "=r"(a) : "l"(p));
    return a;
}
__device__ __forceinline__ void cpa16(uint32_t dst, const void* src) {
    asm volatile("cp.async.ca.shared.global [%0], [%1], 16;" :: "r"(dst), "l"(src));
}
#define CP_COMMIT() asm volatile("cp.async.commit_group;" ::: "memory")
#define CP_WAIT(n)  asm volatile("cp.async.wait_group %0;" :: "n"(n) : "memory")

__device__ __forceinline__ void mma16816(float* c, const uint32_t* a, uint32_t b0, uint32_t b1) {
    asm volatile(
        "mma.sync.aligned.m16n8k16.row.col.f32.bf16.bf16.f32 "
        "{%0,%1,%2,%3}, {%4,%5,%6,%7}, {%8,%9}, {%0,%1,%2,%3};\n"
        : "+f"(c[0]), "+f"(c[1]), "+f"(c[2]), "+f"(c[3])
        : "r"(a[0]), "r"(a[1]), "r"(a[2]), "r"(a[3]), "r"(b0), "r"(b1));
}
__device__ __forceinline__ void ldsm4(uint32_t* r, uint32_t addr) {
    asm volatile("ldmatrix.sync.aligned.m8n8.x4.shared.b16 {%0,%1,%2,%3}, [%4];"
        : "=r"(r[0]), "=r"(r[1]), "=r"(r[2]), "=r"(r[3]) : "r"(addr));
}

// ---------------- stage 0: sigmoid + transpose of adjacency --------------
__global__ void prep_adj_kernel(const float* __restrict__ logits, float* __restrict__ adjT) {
    int idx = blockIdx.x * 256 + threadIdx.x;
    if (idx >= V_*V_*LP1_) return;
    int s = idx % V_;
    int r = idx / V_;
    int l = r % LP1_;
    int i = r / LP1_;
    float x = logits[(s*V_ + i)*LP1_ + l];
    adjT[idx] = 1.f / (1.f + __expf(-x));
}

// -------- Bemb^T[h][k] = var_emb[k][h] (k<64) | temp_emb[k-64][h] | 0 ------
__global__ void prep_bemb_kernel(const float* __restrict__ var_emb,
                                 const float* __restrict__ temp_emb,
                                 __nv_bfloat16* __restrict__ bh,
                                 __nv_bfloat16* __restrict__ bl) {
    int idx = blockIdx.x * 256 + threadIdx.x;
    if (idx >= H_*80) return;
    int h = idx / 80, k = idx % 80;
    float f = 0.f;
    if (k < 64)      f = var_emb[(size_t)k*H_ + h];
    else if (k < 75) f = temp_emb[(size_t)(k-64)*H_ + h];
    __nv_bfloat16 hb = __float2bfloat16(f);
    float rl = f - __bfloat162float(hb);
    bh[idx] = hb;
    bl[idx] = __float2bfloat16(rl);
}

// ------- weight transpose+split: wt[slot*64+v][n][k] = W[..][k][n] --------
__global__ void prep_w_kernel(const float* __restrict__ mW,
                              const float* __restrict__ Wq, const float* __restrict__ Wk,
                              const float* __restrict__ Wv, const float* __restrict__ Wo,
                              __nv_bfloat16* __restrict__ whi, __nv_bfloat16* __restrict__ wlo) {
    int sv = blockIdx.z;
    int s = sv >> 6, v = sv & 63;
    const float* src;
    if (s < 3)       src = mW + ((size_t)(v*NL_ + s))*H_*H_;
    else if (s == 3) src = Wq + (size_t)v*H_*H_;
    else if (s == 4) src = Wk + (size_t)v*H_*H_;
    else if (s == 5) src = Wv + (size_t)v*H_*H_;
    else             src = Wo + (size_t)v*H_*H_;
    __shared__ float t[32][33];
    int nbase = blockIdx.x*32, kbase = blockIdx.y*32;
    int tx = threadIdx.x, ty = threadIdx.y;
    #pragma unroll
    for (int j = 0; j < 4; j++)
        t[ty + j*8][tx] = src[(size_t)(kbase + ty + j*8)*H_ + nbase + tx];
    __syncthreads();
    size_t obase = (size_t)sv*H_*H_;
    #pragma unroll
    for (int j = 0; j < 4; j++) {
        int n = nbase + ty + j*8;
        int k = kbase + tx;
        float f = t[tx][ty + j*8];
        __nv_bfloat16 hb = __float2bfloat16(f);
        float rl = f - __bfloat162float(hb);
        __nv_bfloat16 lb = __float2bfloat16(rl);
        whi[obase + (size_t)n*H_ + k] = hb;
        wlo[obase + (size_t)n*H_ + k] = lb;
    }
}

// ---------------- stage 1 (tensor-core): z = [A|Bl] @ Bemb ------------------
// smem: xw 2816 | A hi 11264 | A lo 11264 | B hi 22528 | B lo 22528 = 70400
#define S1_XW  0
#define S1_AH  2816
#define S1_AL  (S1_AH + 11264)
#define S1_BH  (S1_AL + 11264)
#define S1_BL  (S1_BH + 22528)
#define S1_GSM (S1_BL + 22528)   // 70400
#define S1_LDA 88                // bf16 per A row (80 data + 8 pad)
#define S1_PWB 44                // u32 per B row (40 data + 4 pad)

__global__ __launch_bounds__(256, 2)
void stage1_mma(const float* __restrict__ x, const float* __restrict__ adjT,
                const __nv_bfloat16* __restrict__ bembh,
                const __nv_bfloat16* __restrict__ bembl,
                float* __restrict__ z) {
    extern __shared__ char smem[];
    uint32_t sbase = smem_u32(smem);
    int bt = blockIdx.x;
    int b = bt >> 8;
    int t = bt & 255;
    int tid = threadIdx.x, w = tid >> 5, lane = tid & 31;

    // prefetch Bemb (hi+lo): 128 rows x 10 segs of 16B
    #pragma unroll
    for (int i = 0; i < 5; i++) {
        int f = tid + 256*i;
        int n = f / 10, seg = f % 10;
        uint32_t so = (uint32_t)n*(S1_PWB*4) + seg*16;
        cpa16(sbase + S1_BH + so, bembh + (size_t)n*80 + seg*8);
        cpa16(sbase + S1_BL + so, bembl + (size_t)n*80 + seg*8);
    }
    CP_COMMIT();

    float* xw = (float*)(smem + S1_XW);   // [11][64]
    for (int p = tid; p < LP1_*V_; p += 256) {
        int l = p >> 6, s = p & 63;
        int tt = t - l;
        xw[l*V_ + s] = (tt >= 0) ? x[((size_t)(b*S_ + tt))*V_ + s] : 0.f;
    }
    __syncthreads();

    __nv_bfloat16* aH = (__nv_bfloat16*)(smem + S1_AH);
    __nv_bfloat16* aL = (__nv_bfloat16*)(smem + S1_AL);

    // A[i][s] pairs: 64 rows x 32 pairs
    #pragma unroll
    for (int i = 0; i < 8; i++) {
        int f = tid + 256*i;
        int row = f >> 5, pr = f & 31;
        int s0 = pr*2;
        const float* ap = adjT + (size_t)row*LP1_*V_;
        float a0 = 0.f, a1 = 0.f;
        #pragma unroll
        for (int l = 0; l < LP1_; l++) {
            a0 += xw[l*V_ + s0]     * ap[l*V_ + s0];
            a1 += xw[l*V_ + s0 + 1] * ap[l*V_ + s0 + 1];
        }
        uint32_t h, lo;
        pack_trunc2(a0, a1, h, lo);
        int off = row*S1_LDA + s0;
        *(uint32_t*)(aH + off) = h;
        *(uint32_t*)(aL + off) = lo;
    }
    // Bl[i][l] pairs: cols 64..75 (6 pairs per row); col 75 = 0
    if (tid < 128) {
        #pragma unroll
        for (int i = 0; i < 3; i++) {
            int f = tid + 128*i;           // 384 jobs
            int row = f / 6, pj = f % 6;
            int l0 = pj*2;
            const float* ap = adjT + (size_t)row*LP1_*V_;
            float b0 = 0.f, b1 = 0.f;
            #pragma unroll 8
            for (int s = 0; s < V_; s++) {
                b0 += xw[l0*V_ + s] * ap[l0*V_ + s];
                if (l0 + 1 < LP1_) b1 += xw[(l0+1)*V_ + s] * ap[(l0+1)*V_ + s];
            }
            uint32_t h, lo;
            pack_trunc2(b0, b1, h, lo);
            int off = row*S1_LDA + 64 + l0;
            *(uint32_t*)(aH + off) = h;
            *(uint32_t*)(aL + off) = lo;
        }
    } else {
        // zero pad cols 76..79: rows 0..63 x 2 pairs
        int f = tid - 128;
        int row = f >> 1, pj = f & 1;
        int off = row*S1_LDA + 76 + pj*2;
        *(uint32_t*)(aH + off) = 0u;
        *(uint32_t*)(aL + off) = 0u;
    }
    CP_WAIT(0);
    __syncthreads();

    // warp tile: 16 rows x 64 cols. wm = w&3 (i group), wn = w>>2 (h half)
    int wm = w & 3, wn = w >> 2;
    int qd = lane >> 2, mq = lane & 3;
    float acc[8][4];
    #pragma unroll
    for (int nj = 0; nj < 8; nj++)
        #pragma unroll
        for (int e = 0; e < 4; e++) acc[nj][e] = 0.f;

    const uint32_t* wsH = (const uint32_t*)(smem + S1_BH);
    const uint32_t* wsL = (const uint32_t*)(smem + S1_BL);
    uint32_t arow = (uint32_t)(wm*16 + (lane & 15));
    uint32_t acol16 = (uint32_t)((lane >> 4) * 8);

    #pragma unroll
    for (int ks = 0; ks < 5; ks++) {
        uint32_t ah[4], al[4];
        uint32_t off = (arow*S1_LDA + ks*16 + acol16) * 2;
        ldsm4(ah, sbase + S1_AH + off);
        ldsm4(al, sbase + S1_AL + off);
        #pragma unroll
        for (int nj = 0; nj < 8; nj++) {
            int wi = (wn*64 + nj*8 + qd)*S1_PWB + ks*8 + mq;
            uint32_t b0h = wsH[wi], b1h = wsH[wi+4];
            uint32_t b0l = wsL[wi], b1l = wsL[wi+4];
            mma16816(acc[nj], ah, b0h, b1h);
            mma16816(acc[nj], ah, b0l, b1l);
            mma16816(acc[nj], al, b0h, b1h);
        }
    }

    // store z
    int i0 = wm*16 + qd;
    #pragma unroll
    for (int nj = 0; nj < 8; nj++) {
        int col = wn*64 + nj*8 + mq*2;
        *(float2*)(z + ((size_t)bt*V_ + i0)*H_ + col)     = make_float2(acc[nj][0], acc[nj][1]);
        *(float2*)(z + ((size_t)bt*V_ + i0 + 8)*H_ + col) = make_float2(acc[nj][2], acc[nj][3]);
    }
}

// ========= raw-mma GEMM chain: BM=64, 8 warps (warp = 32 rows x 32 cols) ===
#define FP_PAR 0
#define RED    4608
#define FSA_HI 8704
#define FSA_LO (FSA_HI + 17408)
#define FSB0   (FSA_LO + 17408)
#define WBUF   20480
#define FSB1   (FSB0 + WBUF)
#define FGSM   (FSB1 + WBUF)
#define WSHALF 10240
#define PW     20
#define LD2    136

__device__ __forceinline__ void fillA(char* smem, const float* __restrict__ src,
                                      size_t rstr, int tid) {
    __nv_bfloat16* aH = (__nv_bfloat16*)(smem + FSA_HI);
    __nv_bfloat16* aL = (__nv_bfloat16*)(smem + FSA_LO);
    #pragma unroll
    for (int i = 0; i < 8; i++) {
        int f = tid + 256*i;
        int row = f >> 5, c4 = f & 31;
        float4 vv = *(const float4*)(src + (size_t)row*rstr + c4*4);
        uint32_t h0, l0, h1, l1;
        pack_trunc2(vv.x, vv.y, h0, l0);
        pack_trunc2(vv.z, vv.w, h1, l1);
        int off = row*LD2 + c4*4;
        *(uint2*)(aH + off) = make_uint2(h0, h1);
        *(uint2*)(aL + off) = make_uint2(l0, l1);
    }
}

__device__ __forceinline__ void stageW(uint32_t sb, const __nv_bfloat16* __restrict__ hi,
                                       const __nv_bfloat16* __restrict__ lo,
                                       int chunk, int tid) {
    #pragma unroll
    for (int i = 0; i < 2; i++) {
        int f = tid + 256*i;
        int n = f >> 2, seg = f & 3;
        uint32_t so = (uint32_t)n*(PW*4) + seg*16;
        size_t go = (size_t)n*H_ + chunk*32 + seg*8;
        cpa16(sb + so, hi + go);
        cpa16(sb + WSHALF + so, lo + go);
    }
}

__device__ __forceinline__ void mma_chunk(char* smem, uint32_t sbase, int sb, int c,
                                          int wm, int wn, int lane,
                                          float (&acc)[2][4][4]) {
    const uint32_t* ws  = (const uint32_t*)(smem + sb);
    const uint32_t* wsl = (const uint32_t*)(smem + sb + WSHALF);
    uint32_t arow = (uint32_t)(wm*32 + (lane & 15));
    uint32_t acol16 = (uint32_t)((lane >> 4) * 8);
    #pragma unroll
    for (int ks = 0; ks < 2; ks++) {
        int kofs = c*32 + ks*16;
        uint32_t ah[2][4], al[2][4];
        #pragma unroll
        for (int mi = 0; mi < 2; mi++) {
            uint32_t off = ((arow + mi*16)*LD2 + kofs + acol16) * 2;
            ldsm4(ah[mi], sbase + FSA_HI + off);
            ldsm4(al[mi], sbase + FSA_LO + off);
        }
        int wb = (wn*32 + (lane >> 2))*PW + ks*8 + (lane & 3);
        #pragma unroll
        for (int nj = 0; nj < 4; nj++) {
            int wi = wb + nj*8*PW;
            uint32_t b0h = ws[wi],  b1h = ws[wi+4];
            uint32_t b0l = wsl[wi], b1l = wsl[wi+4];
            #pragma unroll
            for (int mi = 0; mi < 2; mi++) {
                mma16816(acc[mi][nj], ah[mi], b0h, b1h);
                mma16816(acc[mi][nj], ah[mi], b0l, b1l);
                mma16816(acc[mi][nj], al[mi], b0h, b1h);
            }
        }
    }
}

__device__ __forceinline__ void layer_chunks(char* smem, uint32_t sbase,
        const __nv_bfloat16* curH, const __nv_bfloat16* curL,
        const __nv_bfloat16* nxtH, const __nv_bfloat16* nxtL, bool has_next,
        int tid, int wm, int wn, int lane, float (&acc)[2][4][4]) {
    #pragma unroll
    for (int mi = 0; mi < 2; mi++)
        #pragma unroll
        for (int nj = 0; nj < 4; nj++)
            #pragma unroll
            for (int e = 0; e < 4; e++) acc[mi][nj][e] = 0.f;
    const int bufs[2] = {FSB0, FSB1};
    #pragma unroll
    for (int c = 0; c < 4; c++) {
        if (c == 3 && !has_next) { CP_WAIT(0); } else { CP_WAIT(1); }
        __syncthreads();
        mma_chunk(smem, sbase, bufs[c&1], c, wm, wn, lane, acc);
        __syncthreads();
        if (c < 2) {
            stageW(sbase + bufs[c&1], curH, curL, c+2, tid);
            CP_COMMIT();
        } else if (has_next) {
            stageW(sbase + bufs[c&1], nxtH, nxtL, c-2, tid);
            CP_COMMIT();
        }
    }
}

// ---------------- fused 6-layer chain: 3 mech + QKV ------------------------
__global__ __launch_bounds__(256, 2)
void fused_chain(const float* __restrict__ z, const float* __restrict__ mech_b,
                 const float* __restrict__ lng, const float* __restrict__ lnb,
                 const __nv_bfloat16* __restrict__ whi, const __nv_bfloat16* __restrict__ wlo,
                 float* __restrict__ qkv) {
    extern __shared__ char smem[];
    uint32_t sbase = smem_u32(smem);
    int tid = threadIdx.x, w = tid >> 5, lane = tid & 31;
    int wm = w & 1, wn = w >> 1;
    int v = blockIdx.y, m0 = blockIdx.x * 64;
    int qd = lane >> 2, mq = lane & 3;

    float* sBias = (float*)(smem + FP_PAR);
    float* sG    = sBias + 384;
    float* sBeta = sG + 384;
    float* rsum  = (float*)(smem + RED);
    float* rsq   = (float*)(smem + RED + 2048);
    if (tid < 128) {
        #pragma unroll
        for (int li = 0; li < 3; li++) {
            sBias[li*128 + tid] = mech_b[(size_t)v*NL_*H_ + li*H_ + tid];
            sG[li*128 + tid]    = lng  [(size_t)v*NL_*H_ + li*H_ + tid];
            sBeta[li*128 + tid] = lnb  [(size_t)v*NL_*H_ + li*H_ + tid];
        }
    }

    size_t slot = (size_t)V_*H_*H_;
    size_t wofs = (size_t)v*H_*H_;
    stageW(sbase + FSB0, whi + wofs, wlo + wofs, 0, tid);
    CP_COMMIT();
    stageW(sbase + FSB1, whi + wofs, wlo + wofs, 1, tid);
    CP_COMMIT();
    fillA(smem, z + ((size_t)m0*V_ + v)*H_, (size_t)V_*H_, tid);

    __nv_bfloat16* aH = (__nv_bfloat16*)(smem + FSA_HI);
    __nv_bfloat16* aL = (__nv_bfloat16*)(smem + FSA_LO);
    float acc[2][4][4];

    #pragma unroll
    for (int li = 0; li < 6; li++) {
        const __nv_bfloat16* curH = whi + (size_t)li*slot + wofs;
        const __nv_bfloat16* curL = wlo + (size_t)li*slot + wofs;
        const __nv_bfloat16* nxtH = whi + (size_t)(li+1)*slot + wofs;
        const __nv_bfloat16* nxtL = wlo + (size_t)(li+1)*slot + wofs;
        layer_chunks(smem, sbase, curH, curL, nxtH, nxtL, li < 5,
                     tid, wm, wn, lane, acc);

        if (li < 3) {
            float bb[4][2];
            #pragma unroll
            for (int nj = 0; nj < 4; nj++) {
                float2 b2 = *(const float2*)(sBias + li*128 + wn*32 + nj*8 + mq*2);
                bb[nj][0] = b2.x; bb[nj][1] = b2.y;
            }
            float s[2][2], q[2][2];
            #pragma unroll
            for (int mi = 0; mi < 2; mi++) {
                s[mi][0]=0.f; s[mi][1]=0.f; q[mi][0]=0.f; q[mi][1]=0.f;
                #pragma unroll
                for (int nj = 0; nj < 4; nj++) {
                    float y0 = acc[mi][nj][0] + bb[nj][0];
                    float y1 = acc[mi][nj][1] + bb[nj][1];
                    float y2 = acc[mi][nj][2] + bb[nj][0];
                    float y3 = acc[mi][nj][3] + bb[nj][1];
                    acc[mi][nj][0]=y0; acc[mi][nj][1]=y1; acc[mi][nj][2]=y2; acc[mi][nj][3]=y3;
                    s[mi][0] += y0+y1; q[mi][0] += y0*y0+y1*y1;
                    s[mi][1] += y2+y3; q[mi][1] += y2*y2+y3*y3;
                }
                #pragma unroll
                for (int h = 0; h < 2; h++) {
                    s[mi][h] += __shfl_xor_sync(0xFFFFFFFFu, s[mi][h], 1);
                    q[mi][h] += __shfl_xor_sync(0xFFFFFFFFu, q[mi][h], 1);
                    s[mi][h] += __shfl_xor_sync(0xFFFFFFFFu, s[mi][h], 2);
                    q[mi][h] += __shfl_xor_sync(0xFFFFFFFFu, q[mi][h], 2);
                }
            }
            if (mq == 0) {
                #pragma unroll
                for (int mi = 0; mi < 2; mi++) {
                    int r0 = wm*32 + mi*16 + qd;
                    rsum[r0*4 + wn]     = s[mi][0];
                    rsq [r0*4 + wn]     = q[mi][0];
                    rsum[(r0+8)*4 + wn] = s[mi][1];
                    rsq [(r0+8)*4 + wn] = q[mi][1];
                }
            }
            __syncthreads();
            float gg[4][2], lb[4][2];
            #pragma unroll
            for (int nj = 0; nj < 4; nj++) {
                float2 g2 = *(const float2*)(sG + li*128 + wn*32 + nj*8 + mq*2);
                float2 l2 = *(const float2*)(sBeta + li*128 + wn*32 + nj*8 + mq*2);
                gg[nj][0]=g2.x; gg[nj][1]=g2.y; lb[nj][0]=l2.x; lb[nj][1]=l2.y;
            }
            #pragma unroll
            for (int mi = 0; mi < 2; mi++) {
                int r0 = wm*32 + mi*16 + qd;
                float4 s4a = *(const float4*)(rsum + r0*4);
                float4 q4a = *(const float4*)(rsq + r0*4);
                float4 s4b = *(const float4*)(rsum + (r0+8)*4);
                float4 q4b = *(const float4*)(rsq + (r0+8)*4);
                float sm0 = s4a.x+s4a.y+s4a.z+s4a.w, sq0 = q4a.x+q4a.y+q4a.z+q4a.w;
                float sm1 = s4b.x+s4b.y+s4b.z+s4b.w, sq1 = q4b.x+q4b.y+q4b.z+q4b.w;
                float mean0 = sm0*(1.f/128.f), var0 = sq0*(1.f/128.f) - mean0*mean0;
                float mean1 = sm1*(1.f/128.f), var1 = sq1*(1.f/128.f) - mean1*mean1;
                float rs0 = rsqrtf(var0 + 1e-5f), rs1 = rsqrtf(var1 + 1e-5f);
                #pragma unroll
                for (int nj = 0; nj < 4; nj++) {
                    float t0 = (acc[mi][nj][0]-mean0)*rs0*gg[nj][0] + lb[nj][0];
                    float t1 = (acc[mi][nj][1]-mean0)*rs0*gg[nj][1] + lb[nj][1];
                    float t2 = (acc[mi][nj][2]-mean1)*rs1*gg[nj][0] + lb[nj][0];
                    float t3 = (acc[mi][nj][3]-mean1)*rs1*gg[nj][1] + lb[nj][1];
                    t0 = 0.5f*t0*(1.f + erff(t0*0.7071067811865476f));
                    t1 = 0.5f*t1*(1.f + erff(t1*0.7071067811865476f));
                    t2 = 0.5f*t2*(1.f + erff(t2*0.7071067811865476f));
                    t3 = 0.5f*t3*(1.f + erff(t3*0.7071067811865476f));
                    int col = wn*32 + nj*8 + mq*2;
                    uint32_t h0, l0, h1, l1;
                    pack_trunc2(t0, t1, h0, l0);
                    pack_trunc2(t2, t3, h1, l1);
                    int oa = r0*LD2 + col;
                    int ob = (r0+8)*LD2 + col;
                    *(uint32_t*)(aH + oa) = h0;  *(uint32_t*)(aL + oa) = l0;
                    *(uint32_t*)(aH + ob) = h1;  *(uint32_t*)(aL + ob) = l1;
                }
            }
            __syncthreads();
        } else {
            float* o = qkv + (size_t)(li-3)*M_*V_*H_;
            #pragma unroll
            for (int mi = 0; mi < 2; mi++) {
                int r0 = m0 + wm*32 + mi*16 + qd;
                #pragma unroll
                for (int nj = 0; nj < 4; nj++) {
                    int col = wn*32 + nj*8 + mq*2;
                    *(float2*)(o + ((size_t)r0*V_ + v)*H_ + col) =
                        make_float2(acc[mi][nj][0], acc[mi][nj][1]);
                    *(float2*)(o + ((size_t)(r0+8)*V_ + v)*H_ + col) =
                        make_float2(acc[mi][nj][2], acc[mi][nj][3]);
                }
            }
        }
    }
}

// ---------------- O-proj + output head -------------------------------------
__global__ __launch_bounds__(256, 2)
void oproj_gemm(const float* __restrict__ att,
                const __nv_bfloat16* __restrict__ whi, const __nv_bfloat16* __restrict__ wlo,
                const float* __restrict__ bo, const float* __restrict__ oW,
                const float* __restrict__ oB, float* __restrict__ out) {
    extern __shared__ char smem[];
    uint32_t sbase = smem_u32(smem);
    int tid = threadIdx.x, w = tid >> 5, lane = tid & 31;
    int wm = w & 1, wn = w >> 1;
    int v = blockIdx.y, m0 = blockIdx.x * 64;
    int qd = lane >> 2, mq = lane & 3;

    float* sBias = (float*)(smem + FP_PAR);
    float* sG    = sBias + 384;
    float* rsum  = (float*)(smem + RED);
    if (tid < 128) {
        sBias[tid] = bo[(size_t)v*H_ + tid];
        sG[tid]    = oW[(size_t)v*H_ + tid];
    }
    size_t wofs = (size_t)6*V_*H_*H_ + (size_t)v*H_*H_;
    stageW(sbase + FSB0, whi + wofs, wlo + wofs, 0, tid);
    CP_COMMIT();
    stageW(sbase + FSB1, whi + wofs, wlo + wofs, 1, tid);
    CP_COMMIT();
    fillA(smem, att + ((size_t)m0*V_ + v)*H_, (size_t)V_*H_, tid);

    float acc[2][4][4];
    layer_chunks(smem, sbase, whi + wofs, wlo + wofs, nullptr, nullptr, false,
                 tid, wm, wn, lane, acc);

    float p[2][2];
    #pragma unroll
    for (int mi = 0; mi < 2; mi++) {
        p[mi][0] = 0.f; p[mi][1] = 0.f;
        #pragma unroll
        for (int nj = 0; nj < 4; nj++) {
            int col = wn*32 + nj*8 + mq*2;
            float2 b2 = *(const float2*)(sBias + col);
            float2 g2 = *(const float2*)(sG + col);
            p[mi][0] += (acc[mi][nj][0]+b2.x)*g2.x + (acc[mi][nj][1]+b2.y)*g2.y;
            p[mi][1] += (acc[mi][nj][2]+b2.x)*g2.x + (acc[mi][nj][3]+b2.y)*g2.y;
        }
        #pragma unroll
        for (int h = 0; h < 2; h++) {
            p[mi][h] += __shfl_xor_sync(0xFFFFFFFFu, p[mi][h], 1);
            p[mi][h] += __shfl_xor_sync(0xFFFFFFFFu, p[mi][h], 2);
        }
    }
    if (mq == 0) {
        #pragma unroll
        for (int mi = 0; mi < 2; mi++) {
            int r0 = wm*32 + mi*16 + qd;
            rsum[r0*4 + wn]     = p[mi][0];
            rsum[(r0+8)*4 + wn] = p[mi][1];
        }
    }
    __syncthreads();
    if (wn == 0 && mq == 0) {
        float ob = oB[v];
        #pragma unroll
        for (int mi = 0; mi < 2; mi++) {
            int r0 = wm*32 + mi*16 + qd;
            float4 a4 = *(const float4*)(rsum + r0*4);
            float4 b4 = *(const float4*)(rsum + (r0+8)*4);
            out[(size_t)(m0+r0)*V_ + v]   = a4.x+a4.y+a4.z+a4.w + ob;
            out[(size_t)(m0+r0+8)*V_ + v] = b4.x+b4.y+b4.z+b4.w + ob;
        }
    }
}

// ================= flash-style mma attention ===============================
#define KSTR 12
#define VSTR 132

__global__ __launch_bounds__(256)
void attn_mma(const float* __restrict__ qkv,
              const float* __restrict__ bq, const float* __restrict__ bk,
              const float* __restrict__ bv, float* __restrict__ out) {
    __shared__ uint32_t khi[256*KSTR], klo[256*KSTR];
    __shared__ uint32_t vthi[16*VSTR], vtlo[16*VSTR];

    int bid = blockIdx.x;
    int n = bid & 7, v = (bid >> 3) & 63, b = bid >> 9;
    int tid = threadIdx.x, w = tid >> 5, lane = tid & 31;

    const float* q  = qkv;
    const float* kk = qkv + (size_t)M_*V_*H_;
    const float* vv = qkv + 2*(size_t)M_*V_*H_;
    size_t rstr = (size_t)V_*H_;
    size_t base = ((size_t)(b*S_)*V_ + v)*H_ + n*DH_;
    size_t bofs = (size_t)v*H_ + n*DH_;

    {
        int key = tid;
        const float4* kp = (const float4*)(kk + base + (size_t)key*rstr);
        const float4* vp = (const float4*)(vv + base + (size_t)key*rstr);
        float kr[16], vr[16];
        #pragma unroll
        for (int i = 0; i < 4; i++) {
            float4 a = kp[i], c = vp[i];
            float4 bb = *(const float4*)(bk + bofs + i*4);
            float4 cb = *(const float4*)(bv + bofs + i*4);
            kr[i*4+0]=a.x+bb.x; kr[i*4+1]=a.y+bb.y; kr[i*4+2]=a.z+bb.z; kr[i*4+3]=a.w+bb.w;
            vr[i*4+0]=c.x+cb.x; vr[i*4+1]=c.y+cb.y; vr[i*4+2]=c.z+cb.z; vr[i*4+3]=c.w+cb.w;
        }
        #pragma unroll
        for (int d = 0; d < 8; d++) {
            uint32_t h = pkrn(kr[2*d], kr[2*d+1]);
            khi[key*KSTR + d] = h;
            klo[key*KSTR + d] = pklo(kr[2*d], kr[2*d+1], h);
        }
        unsigned short* vthi16 = (unsigned short*)vthi;
        unsigned short* vtlo16 = (unsigned short*)vtlo;
        #pragma unroll
        for (int c = 0; c < 16; c++) {
            __nv_bfloat16 hb = __float2bfloat16(vr[c]);
            float lo = vr[c] - __bfloat162float(hb);
            __nv_bfloat16 lb = __float2bfloat16(lo);
            vthi16[c*(2*VSTR) + key] = __bfloat16_as_ushort(hb);
            vtlo16[c*(2*VSTR) + key] = __bfloat16_as_ushort(lb);
        }
    }

    int rq = w*32 + (lane >> 2);
    int c2 = (lane & 3) * 2;
    float2 bq0 = make_float2(bq[bofs + c2],     bq[bofs + c2 + 1]);
    float2 bq1 = make_float2(bq[bofs + c2 + 8], bq[bofs + c2 + 9]);
    uint32_t qhi[2][4], qlo[2][4];
    #pragma unroll
    for (int mi = 0; mi < 2; mi++) {
        int rA = rq + mi*16, rB = rA + 8;
        float2 x00 = *(const float2*)(q + base + (size_t)rA*rstr + c2);
        float2 x01 = *(const float2*)(q + base + (size_t)rA*rstr + c2 + 8);
        float2 x10 = *(const float2*)(q + base + (size_t)rB*rstr + c2);
        float2 x11 = *(const float2*)(q + base + (size_t)rB*rstr + c2 + 8);
        x00.x = (x00.x + bq0.x)*0.25f; x00.y = (x00.y + bq0.y)*0.25f;
        x01.x = (x01.x + bq1.x)*0.25f; x01.y = (x01.y + bq1.y)*0.25f;
        x10.x = (x10.x + bq0.x)*0.25f; x10.y = (x10.y + bq0.y)*0.25f;
        x11.x = (x11.x + bq1.x)*0.25f; x11.y = (x11.y + bq1.y)*0.25f;
        qhi[mi][0] = pkrn(x00.x, x00.y); qlo[mi][0] = pklo(x00.x, x00.y, qhi[mi][0]);
        qhi[mi][1] = pkrn(x10.x, x10.y); qlo[mi][1] = pklo(x10.x, x10.y, qhi[mi][1]);
        qhi[mi][2] = pkrn(x01.x, x01.y); qlo[mi][2] = pklo(x01.x, x01.y, qhi[mi][2]);
        qhi[mi][3] = pkrn(x11.x, x11.y); qlo[mi][3] = pklo(x11.x, x11.y, qhi[mi][3]);
    }
    __syncthreads();

    float oacc[2][2][4];
    #pragma unroll
    for (int mi = 0; mi < 2; mi++)
        #pragma unroll
        for (int d = 0; d < 2; d++)
            #pragma unroll
            for (int e = 0; e < 4; e++) oacc[mi][d][e] = 0.f;
    float mrun[2][2] = {{-1e30f,-1e30f},{-1e30f,-1e30f}};
    float lrun[2][2] = {{0.f,0.f},{0.f,0.f}};

    #pragma unroll
    for (int kt = 0; kt < 4; kt++) {
        int kb = kt * 64;
        uint32_t sbh[8][2], sbl[8][2];
        #pragma unroll
        for (int j = 0; j < 8; j++) {
            int key = kb + j*8 + (lane >> 2);
            int ci  = lane & 3;
            sbh[j][0] = khi[key*KSTR + ci];     sbh[j][1] = khi[key*KSTR + ci + 4];
            sbl[j][0] = klo[key*KSTR + ci];     sbl[j][1] = klo[key*KSTR + ci + 4];
        }
        #pragma unroll
        for (int mi = 0; mi < 2; mi++) {
            float C[8][4];
            #pragma unroll
            for (int j = 0; j < 8; j++) { C[j][0]=0.f; C[j][1]=0.f; C[j][2]=0.f; C[j][3]=0.f; }
            #pragma unroll
            for (int j = 0; j < 8; j++) {
                mma16816(C[j], qhi[mi], sbh[j][0], sbh[j][1]);
                mma16816(C[j], qhi[mi], sbl[j][0], sbl[j][1]);
                mma16816(C[j], qlo[mi], sbh[j][0], sbh[j][1]);
            }
            float mA = -1e30f, mB = -1e30f;
            #pragma unroll
            for (int j = 0; j < 8; j++) {
                mA = fmaxf(mA, fmaxf(C[j][0], C[j][1]));
                mB = fmaxf(mB, fmaxf(C[j][2], C[j][3]));
            }
            mA = fmaxf(mA, __shfl_xor_sync(0xFFFFFFFFu, mA, 1));
            mA = fmaxf(mA, __shfl_xor_sync(0xFFFFFFFFu, mA, 2));
            mB = fmaxf(mB, __shfl_xor_sync(0xFFFFFFFFu, mB, 1));
            mB = fmaxf(mB, __shfl_xor_sync(0xFFFFFFFFu, mB, 2));
            float nA = fmaxf(mrun[mi][0], mA), nB = fmaxf(mrun[mi][1], mB);
            float cA = __expf(mrun[mi][0] - nA), cB = __expf(mrun[mi][1] - nB);
            mrun[mi][0] = nA; mrun[mi][1] = nB;
            float sA = 0.f, sB = 0.f;
            #pragma unroll
            for (int j = 0; j < 8; j++) {
                C[j][0] = __expf(C[j][0] - nA); C[j][1] = __expf(C[j][1] - nA);
                C[j][2] = __expf(C[j][2] - nB); C[j][3] = __expf(C[j][3] - nB);
                sA += C[j][0] + C[j][1];
                sB += C[j][2] + C[j][3];
            }
            sA += __shfl_xor_sync(0xFFFFFFFFu, sA, 1);
            sA += __shfl_xor_sync(0xFFFFFFFFu, sA, 2);
            sB += __shfl_xor_sync(0xFFFFFFFFu, sB, 1);
            sB += __shfl_xor_sync(0xFFFFFFFFu, sB, 2);
            lrun[mi][0] = lrun[mi][0]*cA + sA;
            lrun[mi][1] = lrun[mi][1]*cB + sB;
            #pragma unroll
            for (int d = 0; d < 2; d++) {
                oacc[mi][d][0] *= cA; oacc[mi][d][1] *= cA;
                oacc[mi][d][2] *= cB; oacc[mi][d][3] *= cB;
            }
            #pragma unroll
            for (int u = 0; u < 4; u++) {
                uint32_t pa[4], pl[4];
                pa[0] = pkrn(C[2*u][0],   C[2*u][1]);   pl[0] = pklo(C[2*u][0],   C[2*u][1],   pa[0]);
                pa[1] = pkrn(C[2*u][2],   C[2*u][3]);   pl[1] = pklo(C[2*u][2],   C[2*u][3],   pa[1]);
                pa[2] = pkrn(C[2*u+1][0], C[2*u+1][1]); pl[2] = pklo(C[2*u+1][0], C[2*u+1][1], pa[2]);
                pa[3] = pkrn(C[2*u+1][2], C[2*u+1][3]); pl[3] = pklo(C[2*u+1][2], C[2*u+1][3], pa[3]);
                int kb2h = (kb + u*16) >> 1;
                #pragma unroll
                for (int d = 0; d < 2; d++) {
                    int nrow = d*8 + (lane >> 2);
                    uint32_t b0h = vthi[nrow*VSTR + kb2h + (lane & 3)];
                    uint32_t b1h = vthi[nrow*VSTR + kb2h + 4 + (lane & 3)];
                    uint32_t b0l = vtlo[nrow*VSTR + kb2h + (lane & 3)];
                    uint32_t b1l = vtlo[nrow*VSTR + kb2h + 4 + (lane & 3)];
                    mma16816(oacc[mi][d], pa, b0h, b1h);
                    mma16816(oacc[mi][d], pa, b0l, b1l);
                    mma16816(oacc[mi][d], pl, b0h, b1h);
                }
            }
        }
    }

    #pragma unroll
    for (int mi = 0; mi < 2; mi++) {
        float iA = 1.f / lrun[mi][0], iB = 1.f / lrun[mi][1];
        int rA = w*32 + mi*16 + (lane >> 2), rB = rA + 8;
        #pragma unroll
        for (int d = 0; d < 2; d++) {
            *(float2*)(out + base + (size_t)rA*rstr + d*8 + c2) =
                make_float2(oacc[mi][d][0]*iA, oacc[mi][d][1]*iA);
            *(float2*)(out + base + (size_t)rB*rstr + d*8 + c2) =
                make_float2(oacc[mi][d][2]*iB, oacc[mi][d][3]*iB);
        }
    }
}

// ---------------- launch ---------------------------------------------------
extern "C" void kernel_launch(void* const* d_in, const int* in_sizes, int n_in,
                              void* d_out, int out_size) {
    const float* x       = (const float*)d_in[0];
    const float* adjlog  = (const float*)d_in[1];
    const float* var_emb = (const float*)d_in[2];
    const float* temp_emb= (const float*)d_in[3];
    const float* mech_W  = (const float*)d_in[4];
    const float* mech_b  = (const float*)d_in[5];
    const float* ln_g    = (const float*)d_in[6];
    const float* ln_b    = (const float*)d_in[7];
    const float* Wq      = (const float*)d_in[8];
    const float* Wk      = (const float*)d_in[9];
    const float* Wv      = (const float*)d_in[10];
    const float* Wo      = (const float*)d_in[11];
    const float* bq      = (const float*)d_in[12];
    const float* bk      = (const float*)d_in[13];
    const float* bv      = (const float*)d_in[14];
    const float* bo      = (const float*)d_in[15];
    const float* out_W   = (const float*)d_in[16];
    const float* out_b   = (const float*)d_in[17];
    float* out = (float*)d_out;

    float *adjT, *z, *qkv;
    __nv_bfloat16 *whi, *wlo, *bembh, *bembl;
    cudaGetSymbolAddress((void**)&adjT, g_adjT);
    cudaGetSymbolAddress((void**)&z,    g_z);
    cudaGetSymbolAddress((void**)&qkv,  g_qkv);
    cudaGetSymbolAddress((void**)&whi,  g_whi);
    cudaGetSymbolAddress((void**)&wlo,  g_wlo);
    cudaGetSymbolAddress((void**)&bembh, g_bembh);
    cudaGetSymbolAddress((void**)&bembl, g_bembl);

    cudaFuncSetAttribute(fused_chain, cudaFuncAttributeMaxDynamicSharedMemorySize, FGSM);
    cudaFuncSetAttribute(oproj_gemm,  cudaFuncAttributeMaxDynamicSharedMemorySize, FGSM);
    cudaFuncSetAttribute(stage1_mma,  cudaFuncAttributeMaxDynamicSharedMemorySize, S1_GSM);

    prep_adj_kernel<<<(V_*V_*LP1_ + 255)/256, 256>>>(adjlog, adjT);
    prep_bemb_kernel<<<(H_*80 + 255)/256, 256>>>(var_emb, temp_emb, bembh, bembl);
    prep_w_kernel<<<dim3(4,4,7*V_), dim3(32,8)>>>(mech_W, Wq, Wk, Wv, Wo, whi, wlo);
    stage1_mma<<<M_, 256, S1_GSM>>>(x, adjT, bembh, bembl, z);

    dim3 gg(M_/64, V_);
    fused_chain<<<gg, 256, FGSM>>>(z, mech_b, ln_g, ln_b, whi, wlo, qkv);
    attn_mma<<<B_*V_*NH_, 256>>>(qkv, bq, bk, bv, z);
    oproj_gemm<<<gg, 256, FGSM>>>(z, whi, wlo, bo, out_W, out_b, out);
}